// round 11
// baseline (speedup 1.0000x reference)
#include <cuda_runtime.h>
#include <cuda_fp16.h>
#include <cuda_bf16.h>
#include <cstdint>

#define NMAX 50048
#define EMAX 800000
#define GNUM 512
#define SCAN_B 1024

// ---------------- scratch (device globals; no runtime allocation) -------------
__device__ int   g_degi[NMAX];
__device__ __align__(16) float g_dis[NMAX];
__device__ int   g_offs[NMAX];
__device__ int   g_cursor[NMAX];
__device__ int   g_bsum[64];
__device__ int   g_bbase[64];
__device__ int   g_csrc[EMAX];
__device__ __align__(16) __half g_h0h[NMAX * 128];   // conv1 msg (fp16, unscaled)
__device__ __align__(16) __half g_hwh[NMAX * 128];   // conv2 msg (fp16, pre-scaled by dis)
__device__ __align__(16) __nv_bfloat16 g_w1t_hi[128 * 256];
__device__ __align__(16) __nv_bfloat16 g_w1t_lo[128 * 256];
__device__ __align__(16) __nv_bfloat16 g_w2t_hi[128 * 128];
__device__ __align__(16) __nv_bfloat16 g_w2t_lo[128 * 128];
__device__ __align__(16) float g_sums[GNUM * 64];
__device__ float g_counts[GNUM];

// ---------------- small helpers ------------------------------------------------
__device__ __forceinline__ uint32_t smem_u32(const void* p) {
    uint32_t a;
    asm("{ .reg .u64 t; cvta.to.shared.u64 t, %1; cvt.u32.u64 %0, t; }" : "=r"(a) : "l"(p));
    return a;
}
__device__ __forceinline__ uint32_t pack_bf2(float f0, float f1) {
    __nv_bfloat162 h = __floats2bfloat162_rn(f0, f1);
    return *(uint32_t*)&h;
}

#define LDM4(r0, r1, r2, r3, addr)                                              \
    asm volatile("ldmatrix.sync.aligned.m8n8.x4.shared.b16 {%0,%1,%2,%3}, [%4];" \
                 : "=r"(r0), "=r"(r1), "=r"(r2), "=r"(r3) : "r"(addr))

#define MMA_BF16(d, a, bb0, bb1)                                                 \
    asm volatile("mma.sync.aligned.m16n8k16.row.col.f32.bf16.bf16.f32 "          \
                 "{%0,%1,%2,%3},{%4,%5,%6,%7},{%8,%9},{%0,%1,%2,%3};"            \
                 : "+f"((d)[0]), "+f"((d)[1]), "+f"((d)[2]), "+f"((d)[3])        \
                 : "r"((a)[0]), "r"((a)[1]), "r"((a)[2]), "r"((a)[3]),           \
                   "r"(bb0), "r"(bb1))

// ---------------- init / degree / rsqrt ----------------------------------------
__global__ void k_init(int N) {
    int i = blockIdx.x * blockDim.x + threadIdx.x;
    if (i < N) g_degi[i] = 0;
    if (i < GNUM * 64) g_sums[i] = 0.f;
    if (i < GNUM) g_counts[i] = 0.f;
}
__global__ void k_deg(const int* __restrict__ dst, int E) {
    int e = blockIdx.x * blockDim.x + threadIdx.x;
    if (e < E) atomicAdd(&g_degi[dst[e]], 1);
}
__global__ void k_rsqrt(int N) {
    int i = blockIdx.x * blockDim.x + threadIdx.x;
    if (i < N) g_dis[i] = rsqrtf((float)(g_degi[i] + 1));
}

// ---------------- parallel 3-phase exclusive scan -------------------------------
__global__ void k_scan1(int N) {
    __shared__ int sh[SCAN_B];
    int t = threadIdx.x;
    int i = blockIdx.x * SCAN_B + t;
    int v = (i < N) ? g_degi[i] : 0;
    sh[t] = v;
    __syncthreads();
#pragma unroll
    for (int off = 1; off < SCAN_B; off <<= 1) {
        int u = (t >= off) ? sh[t - off] : 0;
        __syncthreads();
        sh[t] += u;
        __syncthreads();
    }
    if (i < N) g_offs[i] = sh[t] - v;
    if (t == SCAN_B - 1) g_bsum[blockIdx.x] = sh[t];
}
__global__ void k_scan2(int NB) {
    __shared__ int sh[64];
    int t = threadIdx.x;
    int v = (t < NB) ? g_bsum[t] : 0;
    sh[t] = v;
    __syncthreads();
#pragma unroll
    for (int off = 1; off < 64; off <<= 1) {
        int u = (t >= off) ? sh[t - off] : 0;
        __syncthreads();
        sh[t] += u;
        __syncthreads();
    }
    if (t < NB) g_bbase[t] = sh[t] - v;
}
__global__ void k_scan3(int N) {
    int i = blockIdx.x * blockDim.x + threadIdx.x;
    if (i >= N) return;
    int o = g_offs[i] + g_bbase[i >> 10];
    g_offs[i] = o;
    g_cursor[i] = o;
}

// ---------------- CSR fill -------------------------------------------------------
__global__ void k_fill(const int* __restrict__ src, const int* __restrict__ dst, int E) {
    int e = blockIdx.x * blockDim.x + threadIdx.x;
    if (e >= E) return;
    int d = dst[e];
    int p = atomicAdd(&g_cursor[d], 1);
    g_csrc[p] = src[e];
}

// ---------------- weight prep: transpose + bf16 hi/lo split ---------------------
__global__ void k_prep_w1(const float* __restrict__ W1) {
    int i = blockIdx.x * blockDim.x + threadIdx.x;
    if (i >= 128 * 256) return;
    int n = i >> 8, k = i & 255;
    float v = W1[k * 128 + n];
    __nv_bfloat16 h = __float2bfloat16_rn(v);
    __nv_bfloat16 l = __float2bfloat16_rn(v - __bfloat162float(h));
    g_w1t_hi[i] = h;
    g_w1t_lo[i] = l;
}
__global__ void k_prep_wc(const float* __restrict__ W3, const float* __restrict__ W4) {
    int i = blockIdx.x * blockDim.x + threadIdx.x;
    if (i >= 128 * 128) return;
    int n = i >> 7, k = i & 127;
    float v = (n < 64) ? W3[k * 64 + n] : W4[k * 64 + (n - 64)];
    __nv_bfloat16 h = __float2bfloat16_rn(v);
    __nv_bfloat16 l = __float2bfloat16_rn(v - __bfloat162float(h));
    g_w2t_hi[i] = h;
    g_w2t_lo[i] = l;
}

// ---------------- GEMM1: C16[N,128] = fp16(A[N,K]fp32 @ Bt^T) -------------------
#define RSTR 48
#define PLANE 6144
__global__ void __launch_bounds__(256, 2)
k_gemm_mma(const float* __restrict__ A,
           const __nv_bfloat16* __restrict__ Bth, const __nv_bfloat16* __restrict__ Btl,
           __half* __restrict__ C16,
           const float* __restrict__ scale, int N, int K) {
    extern __shared__ char smem[];
    uint32_t sbase = smem_u32(smem);
    const uint32_t SB_OFF = 24576;

    int tid = threadIdx.x;
    int lane = tid & 31;
    int wid = tid >> 5;
    int wr = wid >> 1;
    int wc = wid & 1;
    int row0 = blockIdx.x * 128;

    int ld_row = tid >> 1;
    int ld_half = tid & 1;
    uint32_t ld_soff = (uint32_t)(ld_row * RSTR + ld_half * 16);

    int g = lane >> 3;
    int a_lr = (lane & 7) + ((g & 1) ? 8 : 0);
    int a_kb = (g >> 1) * 16;
    uint32_t a_loff = (uint32_t)(a_lr * RSTR + a_kb);
    int b_nr = (lane & 7) + ((g >> 1) ? 8 : 0);
    int b_kb = (g & 1) * 16;
    uint32_t b_loff = (uint32_t)(b_nr * RSTR + b_kb);

    float acc[2][8][4];
#pragma unroll
    for (int i = 0; i < 2; i++)
#pragma unroll
        for (int j = 0; j < 8; j++)
#pragma unroll
            for (int q = 0; q < 4; q++) acc[i][j][q] = 0.f;

    int nch = K >> 4;

    float4 pA0, pA1;
    uint4 pBh, pBl;

    auto prefetch = [&](int kc) {
        int r = row0 + ld_row;
        int kbase = kc * 16 + ld_half * 8;
        if (r < N) {
            pA0 = *(const float4*)&A[(size_t)r * K + kbase];
            pA1 = *(const float4*)&A[(size_t)r * K + kbase + 4];
        } else {
            pA0 = make_float4(0.f, 0.f, 0.f, 0.f);
            pA1 = pA0;
        }
        pBh = *(const uint4*)&Bth[(size_t)ld_row * K + kbase];
        pBl = *(const uint4*)&Btl[(size_t)ld_row * K + kbase];
    };

    auto store_buf = [&](int buf) {
        uint32_t ab = sbase + (uint32_t)buf * 12288;
        uint4 hi, lo;
        __nv_bfloat16 h, h0;
        float f, rsd, r0;
        f = pA0.x; h0 = __float2bfloat16_rn(f); r0 = f - __bfloat162float(h0);
        f = pA0.y; h = __float2bfloat16_rn(f); rsd = f - __bfloat162float(h);
        hi.x = ((uint32_t)*(unsigned short*)&h0) | (((uint32_t)*(unsigned short*)&h) << 16);
        lo.x = pack_bf2(r0, rsd);
        f = pA0.z; h0 = __float2bfloat16_rn(f); r0 = f - __bfloat162float(h0);
        f = pA0.w; h = __float2bfloat16_rn(f); rsd = f - __bfloat162float(h);
        hi.y = ((uint32_t)*(unsigned short*)&h0) | (((uint32_t)*(unsigned short*)&h) << 16);
        lo.y = pack_bf2(r0, rsd);
        f = pA1.x; h0 = __float2bfloat16_rn(f); r0 = f - __bfloat162float(h0);
        f = pA1.y; h = __float2bfloat16_rn(f); rsd = f - __bfloat162float(h);
        hi.z = ((uint32_t)*(unsigned short*)&h0) | (((uint32_t)*(unsigned short*)&h) << 16);
        lo.z = pack_bf2(r0, rsd);
        f = pA1.z; h0 = __float2bfloat16_rn(f); r0 = f - __bfloat162float(h0);
        f = pA1.w; h = __float2bfloat16_rn(f); rsd = f - __bfloat162float(h);
        hi.w = ((uint32_t)*(unsigned short*)&h0) | (((uint32_t)*(unsigned short*)&h) << 16);
        lo.w = pack_bf2(r0, rsd);
        asm volatile("st.shared.v4.b32 [%0], {%1,%2,%3,%4};" :: "r"(ab + ld_soff),
                     "r"(hi.x), "r"(hi.y), "r"(hi.z), "r"(hi.w) : "memory");
        asm volatile("st.shared.v4.b32 [%0], {%1,%2,%3,%4};" :: "r"(ab + PLANE + ld_soff),
                     "r"(lo.x), "r"(lo.y), "r"(lo.z), "r"(lo.w) : "memory");
        uint32_t bb = sbase + SB_OFF + (uint32_t)buf * 12288;
        asm volatile("st.shared.v4.b32 [%0], {%1,%2,%3,%4};" :: "r"(bb + ld_soff),
                     "r"(pBh.x), "r"(pBh.y), "r"(pBh.z), "r"(pBh.w) : "memory");
        asm volatile("st.shared.v4.b32 [%0], {%1,%2,%3,%4};" :: "r"(bb + PLANE + ld_soff),
                     "r"(pBl.x), "r"(pBl.y), "r"(pBl.z), "r"(pBl.w) : "memory");
    };

    prefetch(0);
    store_buf(0);
    __syncthreads();

    for (int ch = 0; ch < nch; ch++) {
        if (ch + 1 < nch) prefetch(ch + 1);

        uint32_t ab = sbase + (uint32_t)(ch & 1) * 12288;
        uint32_t bb = sbase + SB_OFF + (uint32_t)(ch & 1) * 12288;

        uint32_t ah[2][4], al[2][4];
#pragma unroll
        for (int rt = 0; rt < 2; rt++) {
            uint32_t base = ab + (uint32_t)((wr * 32 + rt * 16) * RSTR) + a_loff;
            LDM4(ah[rt][0], ah[rt][1], ah[rt][2], ah[rt][3], base);
            LDM4(al[rt][0], al[rt][1], al[rt][2], al[rt][3], base + PLANE);
        }

#pragma unroll
        for (int bg = 0; bg < 4; bg++) {
            uint32_t bbase_g = bb + (uint32_t)((wc * 64 + bg * 16) * RSTR) + b_loff;
            uint32_t bh[4], bl[4];
            LDM4(bh[0], bh[1], bh[2], bh[3], bbase_g);
            LDM4(bl[0], bl[1], bl[2], bl[3], bbase_g + PLANE);
#pragma unroll
            for (int rt = 0; rt < 2; rt++) {
#pragma unroll
                for (int sub = 0; sub < 2; sub++) {
                    int nt = bg * 2 + sub;
                    MMA_BF16(acc[rt][nt], ah[rt], bh[sub * 2], bh[sub * 2 + 1]);
                    MMA_BF16(acc[rt][nt], al[rt], bh[sub * 2], bh[sub * 2 + 1]);
                    MMA_BF16(acc[rt][nt], ah[rt], bl[sub * 2], bl[sub * 2 + 1]);
                }
            }
        }

        if (ch + 1 < nch) {
            __syncthreads();
            store_buf((ch + 1) & 1);
            __syncthreads();
        }
    }

#pragma unroll
    for (int rt = 0; rt < 2; rt++) {
        int r_lo = row0 + wr * 32 + rt * 16 + (lane >> 2);
        int r_hi = r_lo + 8;
        float s_lo = 1.f, s_hi = 1.f;
        if (scale) {
            if (r_lo < N) s_lo = __ldg(&scale[r_lo]);
            if (r_hi < N) s_hi = __ldg(&scale[r_hi]);
        }
#pragma unroll
        for (int nt = 0; nt < 8; nt++) {
            int col = wc * 64 + nt * 8 + (lane & 3) * 2;
            float* d = acc[rt][nt];
            if (r_lo < N) {
                __half2 hh = __floats2half2_rn(d[0] * s_lo, d[1] * s_lo);
                *(uint32_t*)&C16[(size_t)r_lo * 128 + col] = *(uint32_t*)&hh;
            }
            if (r_hi < N) {
                __half2 hh = __floats2half2_rn(d[2] * s_hi, d[3] * s_hi);
                *(uint32_t*)&C16[(size_t)r_hi * 128 + col] = *(uint32_t*)&hh;
            }
        }
    }
}

// ---------------- half-warp gather accumulate helpers ---------------------------
__device__ __forceinline__ void hacc(uint4 v, float n, float acc[8]) {
    float2 f;
    f = __half22float2(*(__half2*)&v.x); acc[0] = fmaf(f.x, n, acc[0]); acc[1] = fmaf(f.y, n, acc[1]);
    f = __half22float2(*(__half2*)&v.y); acc[2] = fmaf(f.x, n, acc[2]); acc[3] = fmaf(f.y, n, acc[3]);
    f = __half22float2(*(__half2*)&v.z); acc[4] = fmaf(f.x, n, acc[4]); acc[5] = fmaf(f.y, n, acc[5]);
    f = __half22float2(*(__half2*)&v.w); acc[6] = fmaf(f.x, n, acc[6]); acc[7] = fmaf(f.y, n, acc[7]);
}
__device__ __forceinline__ void hacc1(uint4 v, float acc[8]) {
    float2 f;
    f = __half22float2(*(__half2*)&v.x); acc[0] += f.x; acc[1] += f.y;
    f = __half22float2(*(__half2*)&v.y); acc[2] += f.x; acc[3] += f.y;
    f = __half22float2(*(__half2*)&v.z); acc[4] += f.x; acc[5] += f.y;
    f = __half22float2(*(__half2*)&v.w); acc[6] += f.x; acc[7] += f.y;
}

// ---------------- FUSED conv1-aggregate + GEMM2 ---------------------------------
// Phase 1: 8 warps gather/aggregate 16 nodes each (conv1 epilogue: bias+relu+self),
//          write h as bf16 hi/lo into SMEM A (272B row stride).
// Phase 2: 128x128x128 HMMA GEMM, A from SMEM, B (pre-split W2) double-buffered.
//          Epilogue writes dis-scaled fp16 conv2 messages.
#define ARSTR 272
#define APLANE 34816            // 128 * 272
#define FB_OFF 69632            // 2 * APLANE (128-aligned)
__global__ void __launch_bounds__(256, 2)
k_fused(const float* __restrict__ b1,
        const __nv_bfloat16* __restrict__ Bth, const __nv_bfloat16* __restrict__ Btl,
        __half* __restrict__ C16, const float* __restrict__ scale, int N) {
    extern __shared__ char smem[];
    uint32_t sbase = smem_u32(smem);
    int tid = threadIdx.x;
    int lane = tid & 31;
    int wid = tid >> 5;
    int row0 = blockIdx.x * 128;
    const int K = 128;

    // ---------------- phase 1: gather + conv1 epilogue into SMEM ---------------
    {
        int hh = lane >> 4;
        int sub = lane & 15;
        float4 ba = *(const float4*)&b1[sub * 8];
        float4 bbv = *(const float4*)&b1[sub * 8 + 4];
        for (int i = 0; i < 16; i++) {
            int local = i * 8 + wid;
            int node = row0 + local;
            uint32_t arow = sbase + (uint32_t)local * ARSTR + sub * 16;
            if (node >= N) {
                if (hh == 0) {
                    asm volatile("st.shared.v4.b32 [%0], {%1,%1,%1,%1};" :: "r"(arow), "r"(0u) : "memory");
                    asm volatile("st.shared.v4.b32 [%0], {%1,%1,%1,%1};" :: "r"(arow + APLANE), "r"(0u) : "memory");
                }
                continue;
            }
            float din = g_dis[node];
            int beg = g_offs[node];
            int end = beg + g_degi[node];

            float acc[8] = {0.f, 0.f, 0.f, 0.f, 0.f, 0.f, 0.f, 0.f};
            int j = beg;
            for (; j + 3 < end; j += 4) {
                int sa = __ldg(&g_csrc[j + hh]);
                int sb = __ldg(&g_csrc[j + 2 + hh]);
                uint4 va = __ldg((const uint4*)(g_h0h + (size_t)sa * 128 + sub * 8));
                uint4 vb = __ldg((const uint4*)(g_h0h + (size_t)sb * 128 + sub * 8));
                float na = g_dis[sa] * din;
                float nb = g_dis[sb] * din;
                hacc(va, na, acc);
                hacc(vb, nb, acc);
            }
            for (; j + 1 < end; j += 2) {
                int s = __ldg(&g_csrc[j + hh]);
                uint4 v = __ldg((const uint4*)(g_h0h + (size_t)s * 128 + sub * 8));
                hacc(v, g_dis[s] * din, acc);
            }
            if (j < end && hh == 0) {
                int s = __ldg(&g_csrc[j]);
                uint4 v = __ldg((const uint4*)(g_h0h + (size_t)s * 128 + sub * 8));
                hacc(v, g_dis[s] * din, acc);
            }
#pragma unroll
            for (int k = 0; k < 8; k++)
                acc[k] += __shfl_down_sync(0xffffffffu, acc[k], 16);

            if (hh == 0) {
                float d2 = din * din;
                uint4 sv = *(const uint4*)(g_h0h + (size_t)node * 128 + sub * 8);
                float h0f[8];
                float2 f;
                f = __half22float2(*(__half2*)&sv.x); h0f[0] = f.x; h0f[1] = f.y;
                f = __half22float2(*(__half2*)&sv.y); h0f[2] = f.x; h0f[3] = f.y;
                f = __half22float2(*(__half2*)&sv.z); h0f[4] = f.x; h0f[5] = f.y;
                f = __half22float2(*(__half2*)&sv.w); h0f[6] = f.x; h0f[7] = f.y;
                float r[8];
                r[0] = fmaxf(fmaf(h0f[0], d2, acc[0]) + ba.x, 0.f);
                r[1] = fmaxf(fmaf(h0f[1], d2, acc[1]) + ba.y, 0.f);
                r[2] = fmaxf(fmaf(h0f[2], d2, acc[2]) + ba.z, 0.f);
                r[3] = fmaxf(fmaf(h0f[3], d2, acc[3]) + ba.w, 0.f);
                r[4] = fmaxf(fmaf(h0f[4], d2, acc[4]) + bbv.x, 0.f);
                r[5] = fmaxf(fmaf(h0f[5], d2, acc[5]) + bbv.y, 0.f);
                r[6] = fmaxf(fmaf(h0f[6], d2, acc[6]) + bbv.z, 0.f);
                r[7] = fmaxf(fmaf(h0f[7], d2, acc[7]) + bbv.w, 0.f);
                // split to bf16 hi/lo
                uint4 hi, lo;
                __nv_bfloat16 t0, t1;
                t0 = __float2bfloat16_rn(r[0]); t1 = __float2bfloat16_rn(r[1]);
                hi.x = ((uint32_t)*(unsigned short*)&t0) | (((uint32_t)*(unsigned short*)&t1) << 16);
                lo.x = pack_bf2(r[0] - __bfloat162float(t0), r[1] - __bfloat162float(t1));
                t0 = __float2bfloat16_rn(r[2]); t1 = __float2bfloat16_rn(r[3]);
                hi.y = ((uint32_t)*(unsigned short*)&t0) | (((uint32_t)*(unsigned short*)&t1) << 16);
                lo.y = pack_bf2(r[2] - __bfloat162float(t0), r[3] - __bfloat162float(t1));
                t0 = __float2bfloat16_rn(r[4]); t1 = __float2bfloat16_rn(r[5]);
                hi.z = ((uint32_t)*(unsigned short*)&t0) | (((uint32_t)*(unsigned short*)&t1) << 16);
                lo.z = pack_bf2(r[4] - __bfloat162float(t0), r[5] - __bfloat162float(t1));
                t0 = __float2bfloat16_rn(r[6]); t1 = __float2bfloat16_rn(r[7]);
                hi.w = ((uint32_t)*(unsigned short*)&t0) | (((uint32_t)*(unsigned short*)&t1) << 16);
                lo.w = pack_bf2(r[6] - __bfloat162float(t0), r[7] - __bfloat162float(t1));
                asm volatile("st.shared.v4.b32 [%0], {%1,%2,%3,%4};" :: "r"(arow),
                             "r"(hi.x), "r"(hi.y), "r"(hi.z), "r"(hi.w) : "memory");
                asm volatile("st.shared.v4.b32 [%0], {%1,%2,%3,%4};" :: "r"(arow + APLANE),
                             "r"(lo.x), "r"(lo.y), "r"(lo.z), "r"(lo.w) : "memory");
            }
        }
    }
    __syncthreads();

    // ---------------- phase 2: GEMM from SMEM A -------------------------------
    int wr = wid >> 1;
    int wc = wid & 1;
    int ld_row = tid >> 1;
    int ld_half = tid & 1;
    uint32_t ld_soff = (uint32_t)(ld_row * RSTR + ld_half * 16);

    int g = lane >> 3;
    int a_lr = (lane & 7) + ((g & 1) ? 8 : 0);
    uint32_t a_loff = (uint32_t)(a_lr * ARSTR + (g >> 1) * 16);
    int b_nr = (lane & 7) + ((g >> 1) ? 8 : 0);
    uint32_t b_loff = (uint32_t)(b_nr * RSTR + (g & 1) * 16);

    float acc[2][8][4];
#pragma unroll
    for (int i = 0; i < 2; i++)
#pragma unroll
        for (int j = 0; j < 8; j++)
#pragma unroll
            for (int q = 0; q < 4; q++) acc[i][j][q] = 0.f;

    uint4 pBh, pBl;
    auto prefetchB = [&](int kc) {
        int kbase = kc * 16 + ld_half * 8;
        pBh = *(const uint4*)&Bth[(size_t)ld_row * K + kbase];
        pBl = *(const uint4*)&Btl[(size_t)ld_row * K + kbase];
    };
    auto storeB = [&](int buf) {
        uint32_t bb = sbase + FB_OFF + (uint32_t)buf * 12288;
        asm volatile("st.shared.v4.b32 [%0], {%1,%2,%3,%4};" :: "r"(bb + ld_soff),
                     "r"(pBh.x), "r"(pBh.y), "r"(pBh.z), "r"(pBh.w) : "memory");
        asm volatile("st.shared.v4.b32 [%0], {%1,%2,%3,%4};" :: "r"(bb + PLANE + ld_soff),
                     "r"(pBl.x), "r"(pBl.y), "r"(pBl.z), "r"(pBl.w) : "memory");
    };

    prefetchB(0);
    storeB(0);
    __syncthreads();

    const int nch = 8;     // K=128 / 16
    for (int ch = 0; ch < nch; ch++) {
        if (ch + 1 < nch) prefetchB(ch + 1);

        uint32_t bb = sbase + FB_OFF + (uint32_t)(ch & 1) * 12288;

        uint32_t ah[2][4], al[2][4];
#pragma unroll
        for (int rt = 0; rt < 2; rt++) {
            uint32_t base = sbase + (uint32_t)((wr * 32 + rt * 16) * ARSTR) + (uint32_t)(ch * 32) + a_loff;
            LDM4(ah[rt][0], ah[rt][1], ah[rt][2], ah[rt][3], base);
            LDM4(al[rt][0], al[rt][1], al[rt][2], al[rt][3], base + APLANE);
        }

#pragma unroll
        for (int bg = 0; bg < 4; bg++) {
            uint32_t bbase_g = bb + (uint32_t)((wc * 64 + bg * 16) * RSTR) + b_loff;
            uint32_t bh[4], bl[4];
            LDM4(bh[0], bh[1], bh[2], bh[3], bbase_g);
            LDM4(bl[0], bl[1], bl[2], bl[3], bbase_g + PLANE);
#pragma unroll
            for (int rt = 0; rt < 2; rt++) {
#pragma unroll
                for (int sub = 0; sub < 2; sub++) {
                    int nt = bg * 2 + sub;
                    MMA_BF16(acc[rt][nt], ah[rt], bh[sub * 2], bh[sub * 2 + 1]);
                    MMA_BF16(acc[rt][nt], al[rt], bh[sub * 2], bh[sub * 2 + 1]);
                    MMA_BF16(acc[rt][nt], ah[rt], bl[sub * 2], bl[sub * 2 + 1]);
                }
            }
        }

        if (ch + 1 < nch) {
            __syncthreads();
            storeB((ch + 1) & 1);
            __syncthreads();
        }
    }

    // epilogue: dis-scaled fp16 conv2 messages
#pragma unroll
    for (int rt = 0; rt < 2; rt++) {
        int r_lo = row0 + wr * 32 + rt * 16 + (lane >> 2);
        int r_hi = r_lo + 8;
        float s_lo = 1.f, s_hi = 1.f;
        if (r_lo < N) s_lo = __ldg(&scale[r_lo]);
        if (r_hi < N) s_hi = __ldg(&scale[r_hi]);
#pragma unroll
        for (int nt = 0; nt < 8; nt++) {
            int col = wc * 64 + nt * 8 + (lane & 3) * 2;
            float* d = acc[rt][nt];
            if (r_lo < N) {
                __half2 hv = __floats2half2_rn(d[0] * s_lo, d[1] * s_lo);
                *(uint32_t*)&C16[(size_t)r_lo * 128 + col] = *(uint32_t*)&hv;
            }
            if (r_hi < N) {
                __half2 hv = __floats2half2_rn(d[2] * s_hi, d[3] * s_hi);
                *(uint32_t*)&C16[(size_t)r_hi * 128 + col] = *(uint32_t*)&hv;
            }
        }
    }
}

// ---------------- conv2 aggregate (msgs pre-scaled; self = own msg) -------------
__global__ void k_agg2(const float* __restrict__ b3, const float* __restrict__ b4,
                       const float* __restrict__ noise, const int* __restrict__ batch,
                       int N) {
    int node = (blockIdx.x * blockDim.x + threadIdx.x) >> 5;
    int lane = threadIdx.x & 31;
    if (node >= N) return;
    int h = lane >> 4;
    int sub = lane & 15;
    float din = g_dis[node];
    int beg = g_offs[node];
    int end = beg + g_degi[node];

    float acc[8] = {0.f, 0.f, 0.f, 0.f, 0.f, 0.f, 0.f, 0.f};
    int j = beg;
    for (; j + 3 < end; j += 4) {
        int sa = __ldg(&g_csrc[j + h]);
        int sb = __ldg(&g_csrc[j + 2 + h]);
        uint4 va = __ldg((const uint4*)(g_hwh + (size_t)sa * 128 + sub * 8));
        uint4 vb = __ldg((const uint4*)(g_hwh + (size_t)sb * 128 + sub * 8));
        hacc1(va, acc);
        hacc1(vb, acc);
    }
    for (; j + 1 < end; j += 2) {
        int s = __ldg(&g_csrc[j + h]);
        uint4 v = __ldg((const uint4*)(g_hwh + (size_t)s * 128 + sub * 8));
        hacc1(v, acc);
    }
    if (j < end && h == 0) {
        int s = __ldg(&g_csrc[j]);
        uint4 v = __ldg((const uint4*)(g_hwh + (size_t)s * 128 + sub * 8));
        hacc1(v, acc);
    }

#pragma unroll
    for (int k = 0; k < 8; k++)
        acc[k] += __shfl_down_sync(0xffffffffu, acc[k], 16);

    float v[8], e[8];
    if (lane < 16) {
        int c = sub * 8;
        uint4 sv = *(const uint4*)(g_hwh + (size_t)node * 128 + c);
        float2 f;
        f = __half22float2(*(__half2*)&sv.x); acc[0] += f.x; acc[1] += f.y;
        f = __half22float2(*(__half2*)&sv.y); acc[2] += f.x; acc[3] += f.y;
        f = __half22float2(*(__half2*)&sv.z); acc[4] += f.x; acc[5] += f.y;
        f = __half22float2(*(__half2*)&sv.w); acc[6] += f.x; acc[7] += f.y;
        const float* bias = (sub < 8) ? b3 : b4;
        int bc = (sub < 8) ? c : (c - 64);
        float4 ba = *(const float4*)&bias[bc];
        float4 bbv = *(const float4*)&bias[bc + 4];
        v[0] = fmaf(acc[0], din, ba.x);
        v[1] = fmaf(acc[1], din, ba.y);
        v[2] = fmaf(acc[2], din, ba.z);
        v[3] = fmaf(acc[3], din, ba.w);
        v[4] = fmaf(acc[4], din, bbv.x);
        v[5] = fmaf(acc[5], din, bbv.y);
        v[6] = fmaf(acc[6], din, bbv.z);
        v[7] = fmaf(acc[7], din, bbv.w);
#pragma unroll
        for (int k = 0; k < 8; k++) e[k] = expf(v[k]);
    } else {
#pragma unroll
        for (int k = 0; k < 8; k++) { v[k] = 0.f; e[k] = 0.f; }
    }

#pragma unroll
    for (int k = 0; k < 8; k++)
        e[k] = __shfl_down_sync(0xffffffffu, e[k], 8);

    if (lane < 8) {
        int gb = batch[node];
        int c = sub * 8;
        float4 nza = *(const float4*)&noise[(size_t)node * 64 + c];
        float4 nzb = *(const float4*)&noise[(size_t)node * 64 + c + 4];
        float z0 = fmaf(nza.x, e[0], v[0]);
        float z1 = fmaf(nza.y, e[1], v[1]);
        float z2 = fmaf(nza.z, e[2], v[2]);
        float z3 = fmaf(nza.w, e[3], v[3]);
        float z4 = fmaf(nzb.x, e[4], v[4]);
        float z5 = fmaf(nzb.y, e[5], v[5]);
        float z6 = fmaf(nzb.z, e[6], v[6]);
        float z7 = fmaf(nzb.w, e[7], v[7]);
        float* sp = &g_sums[gb * 64 + c];
        asm volatile("red.global.add.v4.f32 [%0], {%1,%2,%3,%4};"
                     :: "l"(sp), "f"(z0), "f"(z1), "f"(z2), "f"(z3) : "memory");
        asm volatile("red.global.add.v4.f32 [%0], {%1,%2,%3,%4};"
                     :: "l"(sp + 4), "f"(z4), "f"(z5), "f"(z6), "f"(z7) : "memory");
        if (lane == 0) atomicAdd(&g_counts[gb], 1.f);
    }
}

// ---------------- head: warp per graph -------------------------------------------
__global__ void k_head(const float* __restrict__ Wfc, const float* __restrict__ bfc,
                       float* __restrict__ out) {
    int g = (blockIdx.x * blockDim.x + threadIdx.x) >> 5;
    int lane = threadIdx.x & 31;
    if (g >= GNUM) return;
    float inv = 1.f / fmaxf(g_counts[g], 1.f);
    float l0 = 0.f, l1 = 0.f, l2 = 0.f, l3 = 0.f;
#pragma unroll
    for (int t = 0; t < 2; t++) {
        int k = lane + t * 32;
        float p = g_sums[g * 64 + k] * inv;
        float4 wv = *(const float4*)&Wfc[k * 4];
        l0 = fmaf(p, wv.x, l0);
        l1 = fmaf(p, wv.y, l1);
        l2 = fmaf(p, wv.z, l2);
        l3 = fmaf(p, wv.w, l3);
    }
#pragma unroll
    for (int off = 16; off; off >>= 1) {
        l0 += __shfl_down_sync(0xffffffffu, l0, off);
        l1 += __shfl_down_sync(0xffffffffu, l1, off);
        l2 += __shfl_down_sync(0xffffffffu, l2, off);
        l3 += __shfl_down_sync(0xffffffffu, l3, off);
    }
    if (lane == 0) {
        l0 += bfc[0]; l1 += bfc[1]; l2 += bfc[2]; l3 += bfc[3];
        float m = fmaxf(fmaxf(l0, l1), fmaxf(l2, l3));
        float s = expf(l0 - m) + expf(l1 - m) + expf(l2 - m) + expf(l3 - m);
        float lse = m + logf(s);
        out[g * 4 + 0] = l0 - lse;
        out[g * 4 + 1] = l1 - lse;
        out[g * 4 + 2] = l2 - lse;
        out[g * 4 + 3] = l3 - lse;
    }
}

// ---------------- launch ------------------------------------------------------------
extern "C" void kernel_launch(void* const* d_in, const int* in_sizes, int n_in,
                              void* d_out, int out_size) {
    const float* x     = (const float*)d_in[0];
    const int*   ei    = (const int*)d_in[1];
    const int*   batch = (const int*)d_in[2];
    const float* W1    = (const float*)d_in[3];
    const float* b1    = (const float*)d_in[4];
    const float* W3    = (const float*)d_in[5];
    const float* b3    = (const float*)d_in[6];
    const float* W4    = (const float*)d_in[7];
    const float* b4    = (const float*)d_in[8];
    const float* Wfc   = (const float*)d_in[9];
    const float* bfc   = (const float*)d_in[10];
    const float* noise = (const float*)d_in[11];
    float* out = (float*)d_out;

    int N = in_sizes[2];
    int E = in_sizes[1] / 2;
    const int* src = ei;
    const int* dst = ei + E;
    int NB = (N + SCAN_B - 1) / SCAN_B;

    float *disp;
    __half *h0hp, *hwhp;
    __nv_bfloat16 *w1h, *w1l, *w2h, *w2l;
    cudaGetSymbolAddress((void**)&h0hp, g_h0h);
    cudaGetSymbolAddress((void**)&hwhp, g_hwh);
    cudaGetSymbolAddress((void**)&disp, g_dis);
    cudaGetSymbolAddress((void**)&w1h, g_w1t_hi);
    cudaGetSymbolAddress((void**)&w1l, g_w1t_lo);
    cudaGetSymbolAddress((void**)&w2h, g_w2t_hi);
    cudaGetSymbolAddress((void**)&w2l, g_w2t_lo);

    static cudaStream_t s_side = nullptr;
    static cudaEvent_t ev_fork = nullptr, ev_join = nullptr;
    static int attr_set = 0;
    if (!s_side) {
        cudaStreamCreateWithFlags(&s_side, cudaStreamNonBlocking);
        cudaEventCreateWithFlags(&ev_fork, cudaEventDisableTiming);
        cudaEventCreateWithFlags(&ev_join, cudaEventDisableTiming);
    }
    if (!attr_set) {
        cudaFuncSetAttribute(k_gemm_mma, cudaFuncAttributeMaxDynamicSharedMemorySize, 49152);
        cudaFuncSetAttribute(k_fused, cudaFuncAttributeMaxDynamicSharedMemorySize, 94208);
        attr_set = 1;
    }

    // fork: CSR build + misc prologue on side stream
    cudaEventRecord(ev_fork, 0);
    cudaStreamWaitEvent(s_side, ev_fork, 0);

    int ithr = (GNUM * 64 > N) ? GNUM * 64 : N;
    k_init<<<(ithr + 255) / 256, 256, 0, s_side>>>(N);
    k_deg<<<(E + 255) / 256, 256, 0, s_side>>>(dst, E);
    k_rsqrt<<<(N + 255) / 256, 256, 0, s_side>>>(N);
    k_scan1<<<NB, SCAN_B, 0, s_side>>>(N);
    k_scan2<<<1, 64, 0, s_side>>>(NB);
    k_scan3<<<(N + 255) / 256, 256, 0, s_side>>>(N);
    k_fill<<<(E + 255) / 256, 256, 0, s_side>>>(src, dst, E);
    k_prep_wc<<<(128 * 128 + 255) / 256, 256, 0, s_side>>>(W3, W4);

    // GEMM1 on main, overlapping the CSR build
    k_prep_w1<<<(128 * 256 + 255) / 256, 256>>>(W1);
    k_gemm_mma<<<(N + 127) / 128, 256, 49152>>>(x, w1h, w1l, h0hp, nullptr, N, 256);

    // join CSR before the fused conv1-agg + GEMM2
    cudaEventRecord(ev_join, s_side);
    cudaStreamWaitEvent(0, ev_join, 0);

    k_fused<<<(N + 127) / 128, 256, 94208>>>(b1, w2h, w2l, hwhp, disp, N);
    k_agg2<<<(N * 32 + 255) / 256, 256>>>(b3, b4, noise, batch, N);
    k_head<<<(GNUM * 32 + 255) / 256, 256>>>(Wfc, bfc, out);
}

// round 12
// speedup vs baseline: 1.0824x; 1.0824x over previous
#include <cuda_runtime.h>
#include <cuda_fp16.h>
#include <cuda_bf16.h>
#include <cstdint>

#define NMAX 50048
#define EMAX 800000
#define GNUM 512
#define SCAN_B 1024

// ---------------- scratch (device globals; no runtime allocation) -------------
__device__ int   g_degi[NMAX];
__device__ __align__(16) float g_dis[NMAX];
__device__ int   g_offs[NMAX];
__device__ int   g_cursor[NMAX];
__device__ int   g_bsum[64];
__device__ int   g_bbase[64];
__device__ int   g_csrc[EMAX];
__device__ __align__(16) __half g_h0h[NMAX * 128];   // conv1 msg (fp16, unscaled)
__device__ __align__(16) float g_h[NMAX * 128];      // relu(conv1) fp32 (GEMM2 in)
__device__ __align__(16) __half g_hwh[NMAX * 128];   // conv2 msg (fp16, pre-scaled by dis)
__device__ __align__(16) __nv_bfloat16 g_w1t_hi[128 * 256];
__device__ __align__(16) __nv_bfloat16 g_w1t_lo[128 * 256];
__device__ __align__(16) __nv_bfloat16 g_w2t_hi[128 * 128];
__device__ __align__(16) __nv_bfloat16 g_w2t_lo[128 * 128];
__device__ __align__(16) float g_sums[GNUM * 64];
__device__ float g_counts[GNUM];

// ---------------- small helpers ------------------------------------------------
__device__ __forceinline__ uint32_t smem_u32(const void* p) {
    uint32_t a;
    asm("{ .reg .u64 t; cvta.to.shared.u64 t, %1; cvt.u32.u64 %0, t; }" : "=r"(a) : "l"(p));
    return a;
}
__device__ __forceinline__ uint32_t pack_bf2(float f0, float f1) {
    __nv_bfloat162 h = __floats2bfloat162_rn(f0, f1);
    return *(uint32_t*)&h;
}

#define LDM4(r0, r1, r2, r3, addr)                                              \
    asm volatile("ldmatrix.sync.aligned.m8n8.x4.shared.b16 {%0,%1,%2,%3}, [%4];" \
                 : "=r"(r0), "=r"(r1), "=r"(r2), "=r"(r3) : "r"(addr))

#define MMA_BF16(d, a, bb0, bb1)                                                 \
    asm volatile("mma.sync.aligned.m16n8k16.row.col.f32.bf16.bf16.f32 "          \
                 "{%0,%1,%2,%3},{%4,%5,%6,%7},{%8,%9},{%0,%1,%2,%3};"            \
                 : "+f"((d)[0]), "+f"((d)[1]), "+f"((d)[2]), "+f"((d)[3])        \
                 : "r"((a)[0]), "r"((a)[1]), "r"((a)[2]), "r"((a)[3]),           \
                   "r"(bb0), "r"(bb1))

// ---------------- init / degree / rsqrt ----------------------------------------
__global__ void k_init(int N) {
    int i = blockIdx.x * blockDim.x + threadIdx.x;
    if (i < N) g_degi[i] = 0;
    if (i < GNUM * 64) g_sums[i] = 0.f;
    if (i < GNUM) g_counts[i] = 0.f;
}
__global__ void k_deg(const int* __restrict__ dst, int E) {
    int e = blockIdx.x * blockDim.x + threadIdx.x;
    if (e < E) atomicAdd(&g_degi[dst[e]], 1);
}
__global__ void k_rsqrt(int N) {
    int i = blockIdx.x * blockDim.x + threadIdx.x;
    if (i < N) g_dis[i] = rsqrtf((float)(g_degi[i] + 1));
}

// ---------------- parallel 3-phase exclusive scan -------------------------------
__global__ void k_scan1(int N) {
    __shared__ int sh[SCAN_B];
    int t = threadIdx.x;
    int i = blockIdx.x * SCAN_B + t;
    int v = (i < N) ? g_degi[i] : 0;
    sh[t] = v;
    __syncthreads();
#pragma unroll
    for (int off = 1; off < SCAN_B; off <<= 1) {
        int u = (t >= off) ? sh[t - off] : 0;
        __syncthreads();
        sh[t] += u;
        __syncthreads();
    }
    if (i < N) g_offs[i] = sh[t] - v;
    if (t == SCAN_B - 1) g_bsum[blockIdx.x] = sh[t];
}
__global__ void k_scan2(int NB) {
    __shared__ int sh[64];
    int t = threadIdx.x;
    int v = (t < NB) ? g_bsum[t] : 0;
    sh[t] = v;
    __syncthreads();
#pragma unroll
    for (int off = 1; off < 64; off <<= 1) {
        int u = (t >= off) ? sh[t - off] : 0;
        __syncthreads();
        sh[t] += u;
        __syncthreads();
    }
    if (t < NB) g_bbase[t] = sh[t] - v;
}
__global__ void k_scan3(int N) {
    int i = blockIdx.x * blockDim.x + threadIdx.x;
    if (i >= N) return;
    int o = g_offs[i] + g_bbase[i >> 10];
    g_offs[i] = o;
    g_cursor[i] = o;
}

// ---------------- CSR fill -------------------------------------------------------
__global__ void k_fill(const int* __restrict__ src, const int* __restrict__ dst, int E) {
    int e = blockIdx.x * blockDim.x + threadIdx.x;
    if (e >= E) return;
    int d = dst[e];
    int p = atomicAdd(&g_cursor[d], 1);
    g_csrc[p] = src[e];
}

// ---------------- weight prep: transpose + bf16 hi/lo split ---------------------
__global__ void k_prep_w1(const float* __restrict__ W1) {
    int i = blockIdx.x * blockDim.x + threadIdx.x;
    if (i >= 128 * 256) return;
    int n = i >> 8, k = i & 255;
    float v = W1[k * 128 + n];
    __nv_bfloat16 h = __float2bfloat16_rn(v);
    __nv_bfloat16 l = __float2bfloat16_rn(v - __bfloat162float(h));
    g_w1t_hi[i] = h;
    g_w1t_lo[i] = l;
}
__global__ void k_prep_wc(const float* __restrict__ W3, const float* __restrict__ W4) {
    int i = blockIdx.x * blockDim.x + threadIdx.x;
    if (i >= 128 * 128) return;
    int n = i >> 7, k = i & 127;
    float v = (n < 64) ? W3[k * 64 + n] : W4[k * 64 + (n - 64)];
    __nv_bfloat16 h = __float2bfloat16_rn(v);
    __nv_bfloat16 l = __float2bfloat16_rn(v - __bfloat162float(h));
    g_w2t_hi[i] = h;
    g_w2t_lo[i] = l;
}

// ---------------- HMMA GEMM: C16[N,128] = fp16((A @ Bt^T) * scale[row]) ---------
#define RSTR 48
#define PLANE 6144
__global__ void __launch_bounds__(256, 2)
k_gemm_mma(const float* __restrict__ A,
           const __nv_bfloat16* __restrict__ Bth, const __nv_bfloat16* __restrict__ Btl,
           __half* __restrict__ C16,
           const float* __restrict__ scale, int N, int K) {
    extern __shared__ char smem[];
    uint32_t sbase = smem_u32(smem);
    const uint32_t SB_OFF = 24576;

    int tid = threadIdx.x;
    int lane = tid & 31;
    int wid = tid >> 5;
    int wr = wid >> 1;
    int wc = wid & 1;
    int row0 = blockIdx.x * 128;

    int ld_row = tid >> 1;
    int ld_half = tid & 1;
    uint32_t ld_soff = (uint32_t)(ld_row * RSTR + ld_half * 16);

    int g = lane >> 3;
    int a_lr = (lane & 7) + ((g & 1) ? 8 : 0);
    int a_kb = (g >> 1) * 16;
    uint32_t a_loff = (uint32_t)(a_lr * RSTR + a_kb);
    int b_nr = (lane & 7) + ((g >> 1) ? 8 : 0);
    int b_kb = (g & 1) * 16;
    uint32_t b_loff = (uint32_t)(b_nr * RSTR + b_kb);

    float acc[2][8][4];
#pragma unroll
    for (int i = 0; i < 2; i++)
#pragma unroll
        for (int j = 0; j < 8; j++)
#pragma unroll
            for (int q = 0; q < 4; q++) acc[i][j][q] = 0.f;

    int nch = K >> 4;

    float4 pA0, pA1;
    uint4 pBh, pBl;

    auto prefetch = [&](int kc) {
        int r = row0 + ld_row;
        int kbase = kc * 16 + ld_half * 8;
        if (r < N) {
            pA0 = *(const float4*)&A[(size_t)r * K + kbase];
            pA1 = *(const float4*)&A[(size_t)r * K + kbase + 4];
        } else {
            pA0 = make_float4(0.f, 0.f, 0.f, 0.f);
            pA1 = pA0;
        }
        pBh = *(const uint4*)&Bth[(size_t)ld_row * K + kbase];
        pBl = *(const uint4*)&Btl[(size_t)ld_row * K + kbase];
    };

    auto store_buf = [&](int buf) {
        uint32_t ab = sbase + (uint32_t)buf * 12288;
        uint4 hi, lo;
        __nv_bfloat16 h, h0;
        float f, rsd, r0;
        f = pA0.x; h0 = __float2bfloat16_rn(f); r0 = f - __bfloat162float(h0);
        f = pA0.y; h = __float2bfloat16_rn(f); rsd = f - __bfloat162float(h);
        hi.x = ((uint32_t)*(unsigned short*)&h0) | (((uint32_t)*(unsigned short*)&h) << 16);
        lo.x = pack_bf2(r0, rsd);
        f = pA0.z; h0 = __float2bfloat16_rn(f); r0 = f - __bfloat162float(h0);
        f = pA0.w; h = __float2bfloat16_rn(f); rsd = f - __bfloat162float(h);
        hi.y = ((uint32_t)*(unsigned short*)&h0) | (((uint32_t)*(unsigned short*)&h) << 16);
        lo.y = pack_bf2(r0, rsd);
        f = pA1.x; h0 = __float2bfloat16_rn(f); r0 = f - __bfloat162float(h0);
        f = pA1.y; h = __float2bfloat16_rn(f); rsd = f - __bfloat162float(h);
        hi.z = ((uint32_t)*(unsigned short*)&h0) | (((uint32_t)*(unsigned short*)&h) << 16);
        lo.z = pack_bf2(r0, rsd);
        f = pA1.z; h0 = __float2bfloat16_rn(f); r0 = f - __bfloat162float(h0);
        f = pA1.w; h = __float2bfloat16_rn(f); rsd = f - __bfloat162float(h);
        hi.w = ((uint32_t)*(unsigned short*)&h0) | (((uint32_t)*(unsigned short*)&h) << 16);
        lo.w = pack_bf2(r0, rsd);
        asm volatile("st.shared.v4.b32 [%0], {%1,%2,%3,%4};" :: "r"(ab + ld_soff),
                     "r"(hi.x), "r"(hi.y), "r"(hi.z), "r"(hi.w) : "memory");
        asm volatile("st.shared.v4.b32 [%0], {%1,%2,%3,%4};" :: "r"(ab + PLANE + ld_soff),
                     "r"(lo.x), "r"(lo.y), "r"(lo.z), "r"(lo.w) : "memory");
        uint32_t bb = sbase + SB_OFF + (uint32_t)buf * 12288;
        asm volatile("st.shared.v4.b32 [%0], {%1,%2,%3,%4};" :: "r"(bb + ld_soff),
                     "r"(pBh.x), "r"(pBh.y), "r"(pBh.z), "r"(pBh.w) : "memory");
        asm volatile("st.shared.v4.b32 [%0], {%1,%2,%3,%4};" :: "r"(bb + PLANE + ld_soff),
                     "r"(pBl.x), "r"(pBl.y), "r"(pBl.z), "r"(pBl.w) : "memory");
    };

    prefetch(0);
    store_buf(0);
    __syncthreads();

    for (int ch = 0; ch < nch; ch++) {
        if (ch + 1 < nch) prefetch(ch + 1);

        uint32_t ab = sbase + (uint32_t)(ch & 1) * 12288;
        uint32_t bb = sbase + SB_OFF + (uint32_t)(ch & 1) * 12288;

        uint32_t ah[2][4], al[2][4];
#pragma unroll
        for (int rt = 0; rt < 2; rt++) {
            uint32_t base = ab + (uint32_t)((wr * 32 + rt * 16) * RSTR) + a_loff;
            LDM4(ah[rt][0], ah[rt][1], ah[rt][2], ah[rt][3], base);
            LDM4(al[rt][0], al[rt][1], al[rt][2], al[rt][3], base + PLANE);
        }

#pragma unroll
        for (int bg = 0; bg < 4; bg++) {
            uint32_t bbase_g = bb + (uint32_t)((wc * 64 + bg * 16) * RSTR) + b_loff;
            uint32_t bh[4], bl[4];
            LDM4(bh[0], bh[1], bh[2], bh[3], bbase_g);
            LDM4(bl[0], bl[1], bl[2], bl[3], bbase_g + PLANE);
#pragma unroll
            for (int rt = 0; rt < 2; rt++) {
#pragma unroll
                for (int sub = 0; sub < 2; sub++) {
                    int nt = bg * 2 + sub;
                    MMA_BF16(acc[rt][nt], ah[rt], bh[sub * 2], bh[sub * 2 + 1]);
                    MMA_BF16(acc[rt][nt], al[rt], bh[sub * 2], bh[sub * 2 + 1]);
                    MMA_BF16(acc[rt][nt], ah[rt], bl[sub * 2], bl[sub * 2 + 1]);
                }
            }
        }

        if (ch + 1 < nch) {
            __syncthreads();
            store_buf((ch + 1) & 1);
            __syncthreads();
        }
    }

    // epilogue: fp16 only (optionally row-scaled)
#pragma unroll
    for (int rt = 0; rt < 2; rt++) {
        int r_lo = row0 + wr * 32 + rt * 16 + (lane >> 2);
        int r_hi = r_lo + 8;
        float s_lo = 1.f, s_hi = 1.f;
        if (scale) {
            if (r_lo < N) s_lo = __ldg(&scale[r_lo]);
            if (r_hi < N) s_hi = __ldg(&scale[r_hi]);
        }
#pragma unroll
        for (int nt = 0; nt < 8; nt++) {
            int col = wc * 64 + nt * 8 + (lane & 3) * 2;
            float* d = acc[rt][nt];
            if (r_lo < N) {
                __half2 hh = __floats2half2_rn(d[0] * s_lo, d[1] * s_lo);
                *(uint32_t*)&C16[(size_t)r_lo * 128 + col] = *(uint32_t*)&hh;
            }
            if (r_hi < N) {
                __half2 hh = __floats2half2_rn(d[2] * s_hi, d[3] * s_hi);
                *(uint32_t*)&C16[(size_t)r_hi * 128 + col] = *(uint32_t*)&hh;
            }
        }
    }
}

// ---------------- half-warp gather accumulate helpers ---------------------------
__device__ __forceinline__ void hacc(uint4 v, float n, float acc[8]) {
    float2 f;
    f = __half22float2(*(__half2*)&v.x); acc[0] = fmaf(f.x, n, acc[0]); acc[1] = fmaf(f.y, n, acc[1]);
    f = __half22float2(*(__half2*)&v.y); acc[2] = fmaf(f.x, n, acc[2]); acc[3] = fmaf(f.y, n, acc[3]);
    f = __half22float2(*(__half2*)&v.z); acc[4] = fmaf(f.x, n, acc[4]); acc[5] = fmaf(f.y, n, acc[5]);
    f = __half22float2(*(__half2*)&v.w); acc[6] = fmaf(f.x, n, acc[6]); acc[7] = fmaf(f.y, n, acc[7]);
}
__device__ __forceinline__ void hacc1(uint4 v, float acc[8]) {
    float2 f;
    f = __half22float2(*(__half2*)&v.x); acc[0] += f.x; acc[1] += f.y;
    f = __half22float2(*(__half2*)&v.y); acc[2] += f.x; acc[3] += f.y;
    f = __half22float2(*(__half2*)&v.z); acc[4] += f.x; acc[5] += f.y;
    f = __half22float2(*(__half2*)&v.w); acc[6] += f.x; acc[7] += f.y;
}

// ---------------- conv1 aggregate over node range [n0, n1) ----------------------
__global__ void k_agg1(const float* __restrict__ b1, int n0, int n1) {
    int node = n0 + ((blockIdx.x * blockDim.x + threadIdx.x) >> 5);
    int lane = threadIdx.x & 31;
    if (node >= n1) return;
    int h = lane >> 4;
    int sub = lane & 15;
    float din = g_dis[node];
    int beg = g_offs[node];
    int end = beg + g_degi[node];

    float acc[8] = {0.f, 0.f, 0.f, 0.f, 0.f, 0.f, 0.f, 0.f};
    int j = beg;
    for (; j + 3 < end; j += 4) {
        int sa = __ldg(&g_csrc[j + h]);
        int sb = __ldg(&g_csrc[j + 2 + h]);
        uint4 va = __ldg((const uint4*)(g_h0h + (size_t)sa * 128 + sub * 8));
        uint4 vb = __ldg((const uint4*)(g_h0h + (size_t)sb * 128 + sub * 8));
        float na = g_dis[sa] * din;
        float nb = g_dis[sb] * din;
        hacc(va, na, acc);
        hacc(vb, nb, acc);
    }
    for (; j + 1 < end; j += 2) {
        int s = __ldg(&g_csrc[j + h]);
        uint4 v = __ldg((const uint4*)(g_h0h + (size_t)s * 128 + sub * 8));
        hacc(v, g_dis[s] * din, acc);
    }
    if (j < end && h == 0) {
        int s = __ldg(&g_csrc[j]);
        uint4 v = __ldg((const uint4*)(g_h0h + (size_t)s * 128 + sub * 8));
        hacc(v, g_dis[s] * din, acc);
    }

#pragma unroll
    for (int k = 0; k < 8; k++)
        acc[k] += __shfl_down_sync(0xffffffffu, acc[k], 16);

    if (lane < 16) {
        float d2 = din * din;
        int c = sub * 8;
        uint4 sv = *(const uint4*)(g_h0h + (size_t)node * 128 + c);
        float h0f[8];
        float2 f;
        f = __half22float2(*(__half2*)&sv.x); h0f[0] = f.x; h0f[1] = f.y;
        f = __half22float2(*(__half2*)&sv.y); h0f[2] = f.x; h0f[3] = f.y;
        f = __half22float2(*(__half2*)&sv.z); h0f[4] = f.x; h0f[5] = f.y;
        f = __half22float2(*(__half2*)&sv.w); h0f[6] = f.x; h0f[7] = f.y;
        float4 ba = *(const float4*)&b1[c];
        float4 bbv = *(const float4*)&b1[c + 4];
        float4 r0, r1;
        r0.x = fmaxf(fmaf(h0f[0], d2, acc[0]) + ba.x, 0.f);
        r0.y = fmaxf(fmaf(h0f[1], d2, acc[1]) + ba.y, 0.f);
        r0.z = fmaxf(fmaf(h0f[2], d2, acc[2]) + ba.z, 0.f);
        r0.w = fmaxf(fmaf(h0f[3], d2, acc[3]) + ba.w, 0.f);
        r1.x = fmaxf(fmaf(h0f[4], d2, acc[4]) + bbv.x, 0.f);
        r1.y = fmaxf(fmaf(h0f[5], d2, acc[5]) + bbv.y, 0.f);
        r1.z = fmaxf(fmaf(h0f[6], d2, acc[6]) + bbv.z, 0.f);
        r1.w = fmaxf(fmaf(h0f[7], d2, acc[7]) + bbv.w, 0.f);
        *(float4*)&g_h[(size_t)node * 128 + c] = r0;
        *(float4*)&g_h[(size_t)node * 128 + c + 4] = r1;
    }
}

// ---------------- conv2 aggregate (msgs pre-scaled; self = own msg) -------------
__global__ void k_agg2(const float* __restrict__ b3, const float* __restrict__ b4,
                       const float* __restrict__ noise, const int* __restrict__ batch,
                       int N) {
    int node = (blockIdx.x * blockDim.x + threadIdx.x) >> 5;
    int lane = threadIdx.x & 31;
    if (node >= N) return;
    int h = lane >> 4;
    int sub = lane & 15;
    float din = g_dis[node];
    int beg = g_offs[node];
    int end = beg + g_degi[node];

    float acc[8] = {0.f, 0.f, 0.f, 0.f, 0.f, 0.f, 0.f, 0.f};
    int j = beg;
    for (; j + 3 < end; j += 4) {
        int sa = __ldg(&g_csrc[j + h]);
        int sb = __ldg(&g_csrc[j + 2 + h]);
        uint4 va = __ldg((const uint4*)(g_hwh + (size_t)sa * 128 + sub * 8));
        uint4 vb = __ldg((const uint4*)(g_hwh + (size_t)sb * 128 + sub * 8));
        hacc1(va, acc);
        hacc1(vb, acc);
    }
    for (; j + 1 < end; j += 2) {
        int s = __ldg(&g_csrc[j + h]);
        uint4 v = __ldg((const uint4*)(g_hwh + (size_t)s * 128 + sub * 8));
        hacc1(v, acc);
    }
    if (j < end && h == 0) {
        int s = __ldg(&g_csrc[j]);
        uint4 v = __ldg((const uint4*)(g_hwh + (size_t)s * 128 + sub * 8));
        hacc1(v, acc);
    }

#pragma unroll
    for (int k = 0; k < 8; k++)
        acc[k] += __shfl_down_sync(0xffffffffu, acc[k], 16);

    float v[8], e[8];
    if (lane < 16) {
        int c = sub * 8;
        uint4 sv = *(const uint4*)(g_hwh + (size_t)node * 128 + c);
        float2 f;
        f = __half22float2(*(__half2*)&sv.x); acc[0] += f.x; acc[1] += f.y;
        f = __half22float2(*(__half2*)&sv.y); acc[2] += f.x; acc[3] += f.y;
        f = __half22float2(*(__half2*)&sv.z); acc[4] += f.x; acc[5] += f.y;
        f = __half22float2(*(__half2*)&sv.w); acc[6] += f.x; acc[7] += f.y;
        const float* bias = (sub < 8) ? b3 : b4;
        int bc = (sub < 8) ? c : (c - 64);
        float4 ba = *(const float4*)&bias[bc];
        float4 bbv = *(const float4*)&bias[bc + 4];
        v[0] = fmaf(acc[0], din, ba.x);
        v[1] = fmaf(acc[1], din, ba.y);
        v[2] = fmaf(acc[2], din, ba.z);
        v[3] = fmaf(acc[3], din, ba.w);
        v[4] = fmaf(acc[4], din, bbv.x);
        v[5] = fmaf(acc[5], din, bbv.y);
        v[6] = fmaf(acc[6], din, bbv.z);
        v[7] = fmaf(acc[7], din, bbv.w);
#pragma unroll
        for (int k = 0; k < 8; k++) e[k] = expf(v[k]);
    } else {
#pragma unroll
        for (int k = 0; k < 8; k++) { v[k] = 0.f; e[k] = 0.f; }
    }

#pragma unroll
    for (int k = 0; k < 8; k++)
        e[k] = __shfl_down_sync(0xffffffffu, e[k], 8);

    if (lane < 8) {
        int gb = batch[node];
        int c = sub * 8;
        float4 nza = *(const float4*)&noise[(size_t)node * 64 + c];
        float4 nzb = *(const float4*)&noise[(size_t)node * 64 + c + 4];
        float z0 = fmaf(nza.x, e[0], v[0]);
        float z1 = fmaf(nza.y, e[1], v[1]);
        float z2 = fmaf(nza.z, e[2], v[2]);
        float z3 = fmaf(nza.w, e[3], v[3]);
        float z4 = fmaf(nzb.x, e[4], v[4]);
        float z5 = fmaf(nzb.y, e[5], v[5]);
        float z6 = fmaf(nzb.z, e[6], v[6]);
        float z7 = fmaf(nzb.w, e[7], v[7]);
        float* sp = &g_sums[gb * 64 + c];
        asm volatile("red.global.add.v4.f32 [%0], {%1,%2,%3,%4};"
                     :: "l"(sp), "f"(z0), "f"(z1), "f"(z2), "f"(z3) : "memory");
        asm volatile("red.global.add.v4.f32 [%0], {%1,%2,%3,%4};"
                     :: "l"(sp + 4), "f"(z4), "f"(z5), "f"(z6), "f"(z7) : "memory");
        if (lane == 0) atomicAdd(&g_counts[gb], 1.f);
    }
}

// ---------------- head: warp per graph -------------------------------------------
__global__ void k_head(const float* __restrict__ Wfc, const float* __restrict__ bfc,
                       float* __restrict__ out) {
    int g = (blockIdx.x * blockDim.x + threadIdx.x) >> 5;
    int lane = threadIdx.x & 31;
    if (g >= GNUM) return;
    float inv = 1.f / fmaxf(g_counts[g], 1.f);
    float l0 = 0.f, l1 = 0.f, l2 = 0.f, l3 = 0.f;
#pragma unroll
    for (int t = 0; t < 2; t++) {
        int k = lane + t * 32;
        float p = g_sums[g * 64 + k] * inv;
        float4 wv = *(const float4*)&Wfc[k * 4];
        l0 = fmaf(p, wv.x, l0);
        l1 = fmaf(p, wv.y, l1);
        l2 = fmaf(p, wv.z, l2);
        l3 = fmaf(p, wv.w, l3);
    }
#pragma unroll
    for (int off = 16; off; off >>= 1) {
        l0 += __shfl_down_sync(0xffffffffu, l0, off);
        l1 += __shfl_down_sync(0xffffffffu, l1, off);
        l2 += __shfl_down_sync(0xffffffffu, l2, off);
        l3 += __shfl_down_sync(0xffffffffu, l3, off);
    }
    if (lane == 0) {
        l0 += bfc[0]; l1 += bfc[1]; l2 += bfc[2]; l3 += bfc[3];
        float m = fmaxf(fmaxf(l0, l1), fmaxf(l2, l3));
        float s = expf(l0 - m) + expf(l1 - m) + expf(l2 - m) + expf(l3 - m);
        float lse = m + logf(s);
        out[g * 4 + 0] = l0 - lse;
        out[g * 4 + 1] = l1 - lse;
        out[g * 4 + 2] = l2 - lse;
        out[g * 4 + 3] = l3 - lse;
    }
}

// ---------------- launch ------------------------------------------------------------
extern "C" void kernel_launch(void* const* d_in, const int* in_sizes, int n_in,
                              void* d_out, int out_size) {
    const float* x     = (const float*)d_in[0];
    const int*   ei    = (const int*)d_in[1];
    const int*   batch = (const int*)d_in[2];
    const float* W1    = (const float*)d_in[3];
    const float* b1    = (const float*)d_in[4];
    const float* W3    = (const float*)d_in[5];
    const float* b3    = (const float*)d_in[6];
    const float* W4    = (const float*)d_in[7];
    const float* b4    = (const float*)d_in[8];
    const float* Wfc   = (const float*)d_in[9];
    const float* bfc   = (const float*)d_in[10];
    const float* noise = (const float*)d_in[11];
    float* out = (float*)d_out;

    int N = in_sizes[2];
    int E = in_sizes[1] / 2;
    const int* src = ei;
    const int* dst = ei + E;
    int NB = (N + SCAN_B - 1) / SCAN_B;

    // 4 chunk boundaries, 128-aligned
    int C = (((N + 3) / 4 + 127) / 128) * 128;
    int cb[5];
    cb[0] = 0;
    for (int i = 1; i < 4; i++) {
        cb[i] = i * C;
        if (cb[i] > N) cb[i] = N;
    }
    cb[4] = N;

    float *hp, *disp;
    __half *h0hp, *hwhp;
    __nv_bfloat16 *w1h, *w1l, *w2h, *w2l;
    cudaGetSymbolAddress((void**)&h0hp, g_h0h);
    cudaGetSymbolAddress((void**)&hp, g_h);
    cudaGetSymbolAddress((void**)&hwhp, g_hwh);
    cudaGetSymbolAddress((void**)&disp, g_dis);
    cudaGetSymbolAddress((void**)&w1h, g_w1t_hi);
    cudaGetSymbolAddress((void**)&w1l, g_w1t_lo);
    cudaGetSymbolAddress((void**)&w2h, g_w2t_hi);
    cudaGetSymbolAddress((void**)&w2l, g_w2t_lo);

    static cudaStream_t s_side = nullptr;
    static cudaEvent_t ev_fork = nullptr, ev_join = nullptr;
    static cudaEvent_t ev_a[4] = {nullptr, nullptr, nullptr, nullptr};
    static int attr_set = 0;
    if (!s_side) {
        cudaStreamCreateWithFlags(&s_side, cudaStreamNonBlocking);
        cudaEventCreateWithFlags(&ev_fork, cudaEventDisableTiming);
        cudaEventCreateWithFlags(&ev_join, cudaEventDisableTiming);
        for (int i = 0; i < 4; i++)
            cudaEventCreateWithFlags(&ev_a[i], cudaEventDisableTiming);
    }
    if (!attr_set) {
        cudaFuncSetAttribute(k_gemm_mma, cudaFuncAttributeMaxDynamicSharedMemorySize, 49152);
        attr_set = 1;
    }

    // fork: CSR build + misc prologue on side stream
    cudaEventRecord(ev_fork, 0);
    cudaStreamWaitEvent(s_side, ev_fork, 0);

    int ithr = (GNUM * 64 > N) ? GNUM * 64 : N;
    k_init<<<(ithr + 255) / 256, 256, 0, s_side>>>(N);
    k_deg<<<(E + 255) / 256, 256, 0, s_side>>>(dst, E);
    k_rsqrt<<<(N + 255) / 256, 256, 0, s_side>>>(N);
    k_scan1<<<NB, SCAN_B, 0, s_side>>>(N);
    k_scan2<<<1, 64, 0, s_side>>>(NB);
    k_scan3<<<(N + 255) / 256, 256, 0, s_side>>>(N);
    k_fill<<<(E + 255) / 256, 256, 0, s_side>>>(src, dst, E);
    k_prep_wc<<<(128 * 128 + 255) / 256, 256, 0, s_side>>>(W3, W4);

    // GEMM1 (full) on main, overlapping the CSR build
    k_prep_w1<<<(128 * 256 + 255) / 256, 256>>>(W1);
    k_gemm_mma<<<(N + 127) / 128, 256, 49152>>>(x, w1h, w1l, h0hp, nullptr, N, 256);

    // join CSR before aggregates
    cudaEventRecord(ev_join, s_side);
    cudaStreamWaitEvent(0, ev_join, 0);

    // ---- 4-chunk pipelined agg1 (side after c0) / GEMM2 (main) ----
    // chunk 0 aggregate on main
    k_agg1<<<((cb[1] - cb[0]) * 32 + 255) / 256, 256>>>(b1, cb[0], cb[1]);
    cudaEventRecord(ev_a[0], 0);

    // chunks 1..3 aggregate on side (serial), overlapping GEMM2 chunks 0..2
    cudaStreamWaitEvent(s_side, ev_a[0], 0);
    for (int i = 1; i < 4; i++) {
        if (cb[i + 1] > cb[i]) {
            k_agg1<<<((cb[i + 1] - cb[i]) * 32 + 255) / 256, 256, 0, s_side>>>(
                b1, cb[i], cb[i + 1]);
        }
        cudaEventRecord(ev_a[i], s_side);
    }

    // GEMM2 chunks on main, each gated on its agg1 chunk
    for (int i = 0; i < 4; i++) {
        if (i > 0) cudaStreamWaitEvent(0, ev_a[i], 0);
        int lo = cb[i], hi = cb[i + 1];
        if (hi > lo) {
            k_gemm_mma<<<((hi - lo) + 127) / 128, 256, 49152>>>(
                hp + (size_t)lo * 128, w2h, w2l, hwhp + (size_t)lo * 128,
                disp + lo, hi - lo, 128);
        }
    }

    // conv2 aggregate + reparam + pool, then head
    k_agg2<<<(N * 32 + 255) / 256, 256>>>(b3, b4, noise, batch, N);
    k_head<<<(GNUM * 32 + 255) / 256, 256>>>(Wfc, bfc, out);
}

// round 13
// speedup vs baseline: 1.1827x; 1.0927x over previous
#include <cuda_runtime.h>
#include <cuda_fp16.h>
#include <cuda_bf16.h>
#include <cstdint>

#define NMAX 50048
#define EMAX 800000
#define GNUM 512
#define SCAN_B 1024

// ---------------- scratch (device globals; no runtime allocation) -------------
__device__ int   g_degi[NMAX];
__device__ __align__(16) float g_dis[NMAX];
__device__ int   g_offs[NMAX];
__device__ int   g_cursor[NMAX];
__device__ int   g_bsum[64];
__device__ int   g_bbase[64];
__device__ int   g_csrc[EMAX];
__device__ __align__(16) __half g_h0h[NMAX * 128];   // conv1 msg (fp16, unscaled)
__device__ __align__(16) float g_h[NMAX * 128];      // relu(conv1) fp32 (GEMM2 in)
__device__ __align__(16) __half g_hwh[NMAX * 128];   // conv2 msg (fp16, pre-scaled by dis)
__device__ __align__(16) __nv_bfloat16 g_w1t_hi[128 * 256];
__device__ __align__(16) __nv_bfloat16 g_w1t_lo[128 * 256];
__device__ __align__(16) __nv_bfloat16 g_w2t_hi[128 * 128];
__device__ __align__(16) __nv_bfloat16 g_w2t_lo[128 * 128];
__device__ __align__(16) float g_sums[GNUM * 64];
__device__ float g_counts[GNUM];

// ---------------- small helpers ------------------------------------------------
__device__ __forceinline__ uint32_t smem_u32(const void* p) {
    uint32_t a;
    asm("{ .reg .u64 t; cvta.to.shared.u64 t, %1; cvt.u32.u64 %0, t; }" : "=r"(a) : "l"(p));
    return a;
}
__device__ __forceinline__ uint32_t pack_bf2(float f0, float f1) {
    __nv_bfloat162 h = __floats2bfloat162_rn(f0, f1);
    return *(uint32_t*)&h;
}

#define LDM4(r0, r1, r2, r3, addr)                                              \
    asm volatile("ldmatrix.sync.aligned.m8n8.x4.shared.b16 {%0,%1,%2,%3}, [%4];" \
                 : "=r"(r0), "=r"(r1), "=r"(r2), "=r"(r3) : "r"(addr))

#define MMA_BF16(d, a, bb0, bb1)                                                 \
    asm volatile("mma.sync.aligned.m16n8k16.row.col.f32.bf16.bf16.f32 "          \
                 "{%0,%1,%2,%3},{%4,%5,%6,%7},{%8,%9},{%0,%1,%2,%3};"            \
                 : "+f"((d)[0]), "+f"((d)[1]), "+f"((d)[2]), "+f"((d)[3])        \
                 : "r"((a)[0]), "r"((a)[1]), "r"((a)[2]), "r"((a)[3]),           \
                   "r"(bb0), "r"(bb1))

// ---------------- init / degree / rsqrt ----------------------------------------
__global__ void k_init(int N) {
    int i = blockIdx.x * blockDim.x + threadIdx.x;
    if (i < N) g_degi[i] = 0;
    if (i < GNUM * 64) g_sums[i] = 0.f;
    if (i < GNUM) g_counts[i] = 0.f;
}
__global__ void k_deg(const int* __restrict__ dst, int E) {
    int e = blockIdx.x * blockDim.x + threadIdx.x;
    if (e < E) atomicAdd(&g_degi[dst[e]], 1);
}
__global__ void k_rsqrt(int N) {
    int i = blockIdx.x * blockDim.x + threadIdx.x;
    if (i < N) g_dis[i] = rsqrtf((float)(g_degi[i] + 1));
}

// ---------------- parallel 3-phase exclusive scan -------------------------------
__global__ void k_scan1(int N) {
    __shared__ int sh[SCAN_B];
    int t = threadIdx.x;
    int i = blockIdx.x * SCAN_B + t;
    int v = (i < N) ? g_degi[i] : 0;
    sh[t] = v;
    __syncthreads();
#pragma unroll
    for (int off = 1; off < SCAN_B; off <<= 1) {
        int u = (t >= off) ? sh[t - off] : 0;
        __syncthreads();
        sh[t] += u;
        __syncthreads();
    }
    if (i < N) g_offs[i] = sh[t] - v;
    if (t == SCAN_B - 1) g_bsum[blockIdx.x] = sh[t];
}
__global__ void k_scan2(int NB) {
    __shared__ int sh[64];
    int t = threadIdx.x;
    int v = (t < NB) ? g_bsum[t] : 0;
    sh[t] = v;
    __syncthreads();
#pragma unroll
    for (int off = 1; off < 64; off <<= 1) {
        int u = (t >= off) ? sh[t - off] : 0;
        __syncthreads();
        sh[t] += u;
        __syncthreads();
    }
    if (t < NB) g_bbase[t] = sh[t] - v;
}
__global__ void k_scan3(int N) {
    int i = blockIdx.x * blockDim.x + threadIdx.x;
    if (i >= N) return;
    int o = g_offs[i] + g_bbase[i >> 10];
    g_offs[i] = o;
    g_cursor[i] = o;
}

// ---------------- CSR fill -------------------------------------------------------
__global__ void k_fill(const int* __restrict__ src, const int* __restrict__ dst, int E) {
    int e = blockIdx.x * blockDim.x + threadIdx.x;
    if (e >= E) return;
    int d = dst[e];
    int p = atomicAdd(&g_cursor[d], 1);
    g_csrc[p] = src[e];
}

// ---------------- weight prep: transpose + bf16 hi/lo split ---------------------
__global__ void k_prep_w1(const float* __restrict__ W1) {
    int i = blockIdx.x * blockDim.x + threadIdx.x;
    if (i >= 128 * 256) return;
    int n = i >> 8, k = i & 255;
    float v = W1[k * 128 + n];
    __nv_bfloat16 h = __float2bfloat16_rn(v);
    __nv_bfloat16 l = __float2bfloat16_rn(v - __bfloat162float(h));
    g_w1t_hi[i] = h;
    g_w1t_lo[i] = l;
}
__global__ void k_prep_wc(const float* __restrict__ W3, const float* __restrict__ W4) {
    int i = blockIdx.x * blockDim.x + threadIdx.x;
    if (i >= 128 * 128) return;
    int n = i >> 7, k = i & 127;
    float v = (n < 64) ? W3[k * 64 + n] : W4[k * 64 + (n - 64)];
    __nv_bfloat16 h = __float2bfloat16_rn(v);
    __nv_bfloat16 l = __float2bfloat16_rn(v - __bfloat162float(h));
    g_w2t_hi[i] = h;
    g_w2t_lo[i] = l;
}

// ---------------- HMMA GEMM: C16[N,128] = fp16((A @ Bt^T) * scale[row]) ---------
#define RSTR 48
#define PLANE 6144
__global__ void __launch_bounds__(256, 2)
k_gemm_mma(const float* __restrict__ A,
           const __nv_bfloat16* __restrict__ Bth, const __nv_bfloat16* __restrict__ Btl,
           __half* __restrict__ C16,
           const float* __restrict__ scale, int N, int K) {
    extern __shared__ char smem[];
    uint32_t sbase = smem_u32(smem);
    const uint32_t SB_OFF = 24576;

    int tid = threadIdx.x;
    int lane = tid & 31;
    int wid = tid >> 5;
    int wr = wid >> 1;
    int wc = wid & 1;
    int row0 = blockIdx.x * 128;

    int ld_row = tid >> 1;
    int ld_half = tid & 1;
    uint32_t ld_soff = (uint32_t)(ld_row * RSTR + ld_half * 16);

    int g = lane >> 3;
    int a_lr = (lane & 7) + ((g & 1) ? 8 : 0);
    int a_kb = (g >> 1) * 16;
    uint32_t a_loff = (uint32_t)(a_lr * RSTR + a_kb);
    int b_nr = (lane & 7) + ((g >> 1) ? 8 : 0);
    int b_kb = (g & 1) * 16;
    uint32_t b_loff = (uint32_t)(b_nr * RSTR + b_kb);

    float acc[2][8][4];
#pragma unroll
    for (int i = 0; i < 2; i++)
#pragma unroll
        for (int j = 0; j < 8; j++)
#pragma unroll
            for (int q = 0; q < 4; q++) acc[i][j][q] = 0.f;

    int nch = K >> 4;

    float4 pA0, pA1;
    uint4 pBh, pBl;

    auto prefetch = [&](int kc) {
        int r = row0 + ld_row;
        int kbase = kc * 16 + ld_half * 8;
        if (r < N) {
            pA0 = *(const float4*)&A[(size_t)r * K + kbase];
            pA1 = *(const float4*)&A[(size_t)r * K + kbase + 4];
        } else {
            pA0 = make_float4(0.f, 0.f, 0.f, 0.f);
            pA1 = pA0;
        }
        pBh = *(const uint4*)&Bth[(size_t)ld_row * K + kbase];
        pBl = *(const uint4*)&Btl[(size_t)ld_row * K + kbase];
    };

    auto store_buf = [&](int buf) {
        uint32_t ab = sbase + (uint32_t)buf * 12288;
        uint4 hi, lo;
        __nv_bfloat16 h, h0;
        float f, rsd, r0;
        f = pA0.x; h0 = __float2bfloat16_rn(f); r0 = f - __bfloat162float(h0);
        f = pA0.y; h = __float2bfloat16_rn(f); rsd = f - __bfloat162float(h);
        hi.x = ((uint32_t)*(unsigned short*)&h0) | (((uint32_t)*(unsigned short*)&h) << 16);
        lo.x = pack_bf2(r0, rsd);
        f = pA0.z; h0 = __float2bfloat16_rn(f); r0 = f - __bfloat162float(h0);
        f = pA0.w; h = __float2bfloat16_rn(f); rsd = f - __bfloat162float(h);
        hi.y = ((uint32_t)*(unsigned short*)&h0) | (((uint32_t)*(unsigned short*)&h) << 16);
        lo.y = pack_bf2(r0, rsd);
        f = pA1.x; h0 = __float2bfloat16_rn(f); r0 = f - __bfloat162float(h0);
        f = pA1.y; h = __float2bfloat16_rn(f); rsd = f - __bfloat162float(h);
        hi.z = ((uint32_t)*(unsigned short*)&h0) | (((uint32_t)*(unsigned short*)&h) << 16);
        lo.z = pack_bf2(r0, rsd);
        f = pA1.z; h0 = __float2bfloat16_rn(f); r0 = f - __bfloat162float(h0);
        f = pA1.w; h = __float2bfloat16_rn(f); rsd = f - __bfloat162float(h);
        hi.w = ((uint32_t)*(unsigned short*)&h0) | (((uint32_t)*(unsigned short*)&h) << 16);
        lo.w = pack_bf2(r0, rsd);
        asm volatile("st.shared.v4.b32 [%0], {%1,%2,%3,%4};" :: "r"(ab + ld_soff),
                     "r"(hi.x), "r"(hi.y), "r"(hi.z), "r"(hi.w) : "memory");
        asm volatile("st.shared.v4.b32 [%0], {%1,%2,%3,%4};" :: "r"(ab + PLANE + ld_soff),
                     "r"(lo.x), "r"(lo.y), "r"(lo.z), "r"(lo.w) : "memory");
        uint32_t bb = sbase + SB_OFF + (uint32_t)buf * 12288;
        asm volatile("st.shared.v4.b32 [%0], {%1,%2,%3,%4};" :: "r"(bb + ld_soff),
                     "r"(pBh.x), "r"(pBh.y), "r"(pBh.z), "r"(pBh.w) : "memory");
        asm volatile("st.shared.v4.b32 [%0], {%1,%2,%3,%4};" :: "r"(bb + PLANE + ld_soff),
                     "r"(pBl.x), "r"(pBl.y), "r"(pBl.z), "r"(pBl.w) : "memory");
    };

    prefetch(0);
    store_buf(0);
    __syncthreads();

    for (int ch = 0; ch < nch; ch++) {
        if (ch + 1 < nch) prefetch(ch + 1);

        uint32_t ab = sbase + (uint32_t)(ch & 1) * 12288;
        uint32_t bb = sbase + SB_OFF + (uint32_t)(ch & 1) * 12288;

        uint32_t ah[2][4], al[2][4];
#pragma unroll
        for (int rt = 0; rt < 2; rt++) {
            uint32_t base = ab + (uint32_t)((wr * 32 + rt * 16) * RSTR) + a_loff;
            LDM4(ah[rt][0], ah[rt][1], ah[rt][2], ah[rt][3], base);
            LDM4(al[rt][0], al[rt][1], al[rt][2], al[rt][3], base + PLANE);
        }

#pragma unroll
        for (int bg = 0; bg < 4; bg++) {
            uint32_t bbase_g = bb + (uint32_t)((wc * 64 + bg * 16) * RSTR) + b_loff;
            uint32_t bh[4], bl[4];
            LDM4(bh[0], bh[1], bh[2], bh[3], bbase_g);
            LDM4(bl[0], bl[1], bl[2], bl[3], bbase_g + PLANE);
#pragma unroll
            for (int rt = 0; rt < 2; rt++) {
#pragma unroll
                for (int sub = 0; sub < 2; sub++) {
                    int nt = bg * 2 + sub;
                    MMA_BF16(acc[rt][nt], ah[rt], bh[sub * 2], bh[sub * 2 + 1]);
                    MMA_BF16(acc[rt][nt], al[rt], bh[sub * 2], bh[sub * 2 + 1]);
                    MMA_BF16(acc[rt][nt], ah[rt], bl[sub * 2], bl[sub * 2 + 1]);
                }
            }
        }

        if (ch + 1 < nch) {
            __syncthreads();
            store_buf((ch + 1) & 1);
            __syncthreads();
        }
    }

    // epilogue: fp16 only (optionally row-scaled)
#pragma unroll
    for (int rt = 0; rt < 2; rt++) {
        int r_lo = row0 + wr * 32 + rt * 16 + (lane >> 2);
        int r_hi = r_lo + 8;
        float s_lo = 1.f, s_hi = 1.f;
        if (scale) {
            if (r_lo < N) s_lo = __ldg(&scale[r_lo]);
            if (r_hi < N) s_hi = __ldg(&scale[r_hi]);
        }
#pragma unroll
        for (int nt = 0; nt < 8; nt++) {
            int col = wc * 64 + nt * 8 + (lane & 3) * 2;
            float* d = acc[rt][nt];
            if (r_lo < N) {
                __half2 hh = __floats2half2_rn(d[0] * s_lo, d[1] * s_lo);
                *(uint32_t*)&C16[(size_t)r_lo * 128 + col] = *(uint32_t*)&hh;
            }
            if (r_hi < N) {
                __half2 hh = __floats2half2_rn(d[2] * s_hi, d[3] * s_hi);
                *(uint32_t*)&C16[(size_t)r_hi * 128 + col] = *(uint32_t*)&hh;
            }
        }
    }
}

// ---------------- half-warp gather accumulate helpers ---------------------------
__device__ __forceinline__ void hacc(uint4 v, float n, float acc[8]) {
    float2 f;
    f = __half22float2(*(__half2*)&v.x); acc[0] = fmaf(f.x, n, acc[0]); acc[1] = fmaf(f.y, n, acc[1]);
    f = __half22float2(*(__half2*)&v.y); acc[2] = fmaf(f.x, n, acc[2]); acc[3] = fmaf(f.y, n, acc[3]);
    f = __half22float2(*(__half2*)&v.z); acc[4] = fmaf(f.x, n, acc[4]); acc[5] = fmaf(f.y, n, acc[5]);
    f = __half22float2(*(__half2*)&v.w); acc[6] = fmaf(f.x, n, acc[6]); acc[7] = fmaf(f.y, n, acc[7]);
}
__device__ __forceinline__ void hacc1(uint4 v, float acc[8]) {
    float2 f;
    f = __half22float2(*(__half2*)&v.x); acc[0] += f.x; acc[1] += f.y;
    f = __half22float2(*(__half2*)&v.y); acc[2] += f.x; acc[3] += f.y;
    f = __half22float2(*(__half2*)&v.z); acc[4] += f.x; acc[5] += f.y;
    f = __half22float2(*(__half2*)&v.w); acc[6] += f.x; acc[7] += f.y;
}

// ---------------- conv1 aggregate over node range [n0, n1) ----------------------
__global__ void k_agg1(const float* __restrict__ b1, int n0, int n1) {
    int node = n0 + ((blockIdx.x * blockDim.x + threadIdx.x) >> 5);
    int lane = threadIdx.x & 31;
    if (node >= n1) return;
    int h = lane >> 4;
    int sub = lane & 15;
    float din = g_dis[node];
    int beg = g_offs[node];
    int end = beg + g_degi[node];

    float acc[8] = {0.f, 0.f, 0.f, 0.f, 0.f, 0.f, 0.f, 0.f};
    int j = beg;
    for (; j + 3 < end; j += 4) {
        int sa = __ldg(&g_csrc[j + h]);
        int sb = __ldg(&g_csrc[j + 2 + h]);
        uint4 va = __ldg((const uint4*)(g_h0h + (size_t)sa * 128 + sub * 8));
        uint4 vb = __ldg((const uint4*)(g_h0h + (size_t)sb * 128 + sub * 8));
        float na = g_dis[sa] * din;
        float nb = g_dis[sb] * din;
        hacc(va, na, acc);
        hacc(vb, nb, acc);
    }
    for (; j + 1 < end; j += 2) {
        int s = __ldg(&g_csrc[j + h]);
        uint4 v = __ldg((const uint4*)(g_h0h + (size_t)s * 128 + sub * 8));
        hacc(v, g_dis[s] * din, acc);
    }
    if (j < end && h == 0) {
        int s = __ldg(&g_csrc[j]);
        uint4 v = __ldg((const uint4*)(g_h0h + (size_t)s * 128 + sub * 8));
        hacc(v, g_dis[s] * din, acc);
    }

#pragma unroll
    for (int k = 0; k < 8; k++)
        acc[k] += __shfl_down_sync(0xffffffffu, acc[k], 16);

    if (lane < 16) {
        float d2 = din * din;
        int c = sub * 8;
        uint4 sv = *(const uint4*)(g_h0h + (size_t)node * 128 + c);
        float h0f[8];
        float2 f;
        f = __half22float2(*(__half2*)&sv.x); h0f[0] = f.x; h0f[1] = f.y;
        f = __half22float2(*(__half2*)&sv.y); h0f[2] = f.x; h0f[3] = f.y;
        f = __half22float2(*(__half2*)&sv.z); h0f[4] = f.x; h0f[5] = f.y;
        f = __half22float2(*(__half2*)&sv.w); h0f[6] = f.x; h0f[7] = f.y;
        float4 ba = *(const float4*)&b1[c];
        float4 bbv = *(const float4*)&b1[c + 4];
        float4 r0, r1;
        r0.x = fmaxf(fmaf(h0f[0], d2, acc[0]) + ba.x, 0.f);
        r0.y = fmaxf(fmaf(h0f[1], d2, acc[1]) + ba.y, 0.f);
        r0.z = fmaxf(fmaf(h0f[2], d2, acc[2]) + ba.z, 0.f);
        r0.w = fmaxf(fmaf(h0f[3], d2, acc[3]) + ba.w, 0.f);
        r1.x = fmaxf(fmaf(h0f[4], d2, acc[4]) + bbv.x, 0.f);
        r1.y = fmaxf(fmaf(h0f[5], d2, acc[5]) + bbv.y, 0.f);
        r1.z = fmaxf(fmaf(h0f[6], d2, acc[6]) + bbv.z, 0.f);
        r1.w = fmaxf(fmaf(h0f[7], d2, acc[7]) + bbv.w, 0.f);
        *(float4*)&g_h[(size_t)node * 128 + c] = r0;
        *(float4*)&g_h[(size_t)node * 128 + c + 4] = r1;
    }
}

// ---------------- conv2 aggregate (msgs pre-scaled; self = own msg) -------------
__global__ void k_agg2(const float* __restrict__ b3, const float* __restrict__ b4,
                       const float* __restrict__ noise, const int* __restrict__ batch,
                       int N) {
    int node = (blockIdx.x * blockDim.x + threadIdx.x) >> 5;
    int lane = threadIdx.x & 31;
    if (node >= N) return;
    int h = lane >> 4;
    int sub = lane & 15;
    float din = g_dis[node];
    int beg = g_offs[node];
    int end = beg + g_degi[node];

    float acc[8] = {0.f, 0.f, 0.f, 0.f, 0.f, 0.f, 0.f, 0.f};
    int j = beg;
    for (; j + 3 < end; j += 4) {
        int sa = __ldg(&g_csrc[j + h]);
        int sb = __ldg(&g_csrc[j + 2 + h]);
        uint4 va = __ldg((const uint4*)(g_hwh + (size_t)sa * 128 + sub * 8));
        uint4 vb = __ldg((const uint4*)(g_hwh + (size_t)sb * 128 + sub * 8));
        hacc1(va, acc);
        hacc1(vb, acc);
    }
    for (; j + 1 < end; j += 2) {
        int s = __ldg(&g_csrc[j + h]);
        uint4 v = __ldg((const uint4*)(g_hwh + (size_t)s * 128 + sub * 8));
        hacc1(v, acc);
    }
    if (j < end && h == 0) {
        int s = __ldg(&g_csrc[j]);
        uint4 v = __ldg((const uint4*)(g_hwh + (size_t)s * 128 + sub * 8));
        hacc1(v, acc);
    }

#pragma unroll
    for (int k = 0; k < 8; k++)
        acc[k] += __shfl_down_sync(0xffffffffu, acc[k], 16);

    float v[8], e[8];
    if (lane < 16) {
        int c = sub * 8;
        uint4 sv = *(const uint4*)(g_hwh + (size_t)node * 128 + c);
        float2 f;
        f = __half22float2(*(__half2*)&sv.x); acc[0] += f.x; acc[1] += f.y;
        f = __half22float2(*(__half2*)&sv.y); acc[2] += f.x; acc[3] += f.y;
        f = __half22float2(*(__half2*)&sv.z); acc[4] += f.x; acc[5] += f.y;
        f = __half22float2(*(__half2*)&sv.w); acc[6] += f.x; acc[7] += f.y;
        const float* bias = (sub < 8) ? b3 : b4;
        int bc = (sub < 8) ? c : (c - 64);
        float4 ba = *(const float4*)&bias[bc];
        float4 bbv = *(const float4*)&bias[bc + 4];
        v[0] = fmaf(acc[0], din, ba.x);
        v[1] = fmaf(acc[1], din, ba.y);
        v[2] = fmaf(acc[2], din, ba.z);
        v[3] = fmaf(acc[3], din, ba.w);
        v[4] = fmaf(acc[4], din, bbv.x);
        v[5] = fmaf(acc[5], din, bbv.y);
        v[6] = fmaf(acc[6], din, bbv.z);
        v[7] = fmaf(acc[7], din, bbv.w);
#pragma unroll
        for (int k = 0; k < 8; k++) e[k] = expf(v[k]);
    } else {
#pragma unroll
        for (int k = 0; k < 8; k++) { v[k] = 0.f; e[k] = 0.f; }
    }

#pragma unroll
    for (int k = 0; k < 8; k++)
        e[k] = __shfl_down_sync(0xffffffffu, e[k], 8);

    if (lane < 8) {
        int gb = batch[node];
        int c = sub * 8;
        float4 nza = *(const float4*)&noise[(size_t)node * 64 + c];
        float4 nzb = *(const float4*)&noise[(size_t)node * 64 + c + 4];
        float z0 = fmaf(nza.x, e[0], v[0]);
        float z1 = fmaf(nza.y, e[1], v[1]);
        float z2 = fmaf(nza.z, e[2], v[2]);
        float z3 = fmaf(nza.w, e[3], v[3]);
        float z4 = fmaf(nzb.x, e[4], v[4]);
        float z5 = fmaf(nzb.y, e[5], v[5]);
        float z6 = fmaf(nzb.z, e[6], v[6]);
        float z7 = fmaf(nzb.w, e[7], v[7]);
        float* sp = &g_sums[gb * 64 + c];
        asm volatile("red.global.add.v4.f32 [%0], {%1,%2,%3,%4};"
                     :: "l"(sp), "f"(z0), "f"(z1), "f"(z2), "f"(z3) : "memory");
        asm volatile("red.global.add.v4.f32 [%0], {%1,%2,%3,%4};"
                     :: "l"(sp + 4), "f"(z4), "f"(z5), "f"(z6), "f"(z7) : "memory");
        if (lane == 0) atomicAdd(&g_counts[gb], 1.f);
    }
}

// ---------------- head: warp per graph -------------------------------------------
__global__ void k_head(const float* __restrict__ Wfc, const float* __restrict__ bfc,
                       float* __restrict__ out) {
    int g = (blockIdx.x * blockDim.x + threadIdx.x) >> 5;
    int lane = threadIdx.x & 31;
    if (g >= GNUM) return;
    float inv = 1.f / fmaxf(g_counts[g], 1.f);
    float l0 = 0.f, l1 = 0.f, l2 = 0.f, l3 = 0.f;
#pragma unroll
    for (int t = 0; t < 2; t++) {
        int k = lane + t * 32;
        float p = g_sums[g * 64 + k] * inv;
        float4 wv = *(const float4*)&Wfc[k * 4];
        l0 = fmaf(p, wv.x, l0);
        l1 = fmaf(p, wv.y, l1);
        l2 = fmaf(p, wv.z, l2);
        l3 = fmaf(p, wv.w, l3);
    }
#pragma unroll
    for (int off = 16; off; off >>= 1) {
        l0 += __shfl_down_sync(0xffffffffu, l0, off);
        l1 += __shfl_down_sync(0xffffffffu, l1, off);
        l2 += __shfl_down_sync(0xffffffffu, l2, off);
        l3 += __shfl_down_sync(0xffffffffu, l3, off);
    }
    if (lane == 0) {
        l0 += bfc[0]; l1 += bfc[1]; l2 += bfc[2]; l3 += bfc[3];
        float m = fmaxf(fmaxf(l0, l1), fmaxf(l2, l3));
        float s = expf(l0 - m) + expf(l1 - m) + expf(l2 - m) + expf(l3 - m);
        float lse = m + logf(s);
        out[g * 4 + 0] = l0 - lse;
        out[g * 4 + 1] = l1 - lse;
        out[g * 4 + 2] = l2 - lse;
        out[g * 4 + 3] = l3 - lse;
    }
}

// ---------------- launch ------------------------------------------------------------
extern "C" void kernel_launch(void* const* d_in, const int* in_sizes, int n_in,
                              void* d_out, int out_size) {
    const float* x     = (const float*)d_in[0];
    const int*   ei    = (const int*)d_in[1];
    const int*   batch = (const int*)d_in[2];
    const float* W1    = (const float*)d_in[3];
    const float* b1    = (const float*)d_in[4];
    const float* W3    = (const float*)d_in[5];
    const float* b3    = (const float*)d_in[6];
    const float* W4    = (const float*)d_in[7];
    const float* b4    = (const float*)d_in[8];
    const float* Wfc   = (const float*)d_in[9];
    const float* bfc   = (const float*)d_in[10];
    const float* noise = (const float*)d_in[11];
    float* out = (float*)d_out;

    int N = in_sizes[2];
    int E = in_sizes[1] / 2;
    const int* src = ei;
    const int* dst = ei + E;
    int NB = (N + SCAN_B - 1) / SCAN_B;
    // chunk0 = ~70% of N (128-aligned): balances side agg1 (30%) vs GEMM2 c0 (70%)
    int Nh = ((int)(0.7f * N + 127) / 128) * 128;
    if (Nh > N) Nh = N;

    float *hp, *disp;
    __half *h0hp, *hwhp;
    __nv_bfloat16 *w1h, *w1l, *w2h, *w2l;
    cudaGetSymbolAddress((void**)&h0hp, g_h0h);
    cudaGetSymbolAddress((void**)&hp, g_h);
    cudaGetSymbolAddress((void**)&hwhp, g_hwh);
    cudaGetSymbolAddress((void**)&disp, g_dis);
    cudaGetSymbolAddress((void**)&w1h, g_w1t_hi);
    cudaGetSymbolAddress((void**)&w1l, g_w1t_lo);
    cudaGetSymbolAddress((void**)&w2h, g_w2t_hi);
    cudaGetSymbolAddress((void**)&w2l, g_w2t_lo);

    static cudaStream_t s_side = nullptr;
    static cudaEvent_t ev_fork = nullptr, ev_join = nullptr, ev_c0 = nullptr, ev_a1 = nullptr;
    static int attr_set = 0;
    if (!s_side) {
        cudaStreamCreateWithFlags(&s_side, cudaStreamNonBlocking);
        cudaEventCreateWithFlags(&ev_fork, cudaEventDisableTiming);
        cudaEventCreateWithFlags(&ev_join, cudaEventDisableTiming);
        cudaEventCreateWithFlags(&ev_c0, cudaEventDisableTiming);
        cudaEventCreateWithFlags(&ev_a1, cudaEventDisableTiming);
    }
    if (!attr_set) {
        cudaFuncSetAttribute(k_gemm_mma, cudaFuncAttributeMaxDynamicSharedMemorySize, 49152);
        attr_set = 1;
    }

    // fork: CSR build + misc prologue on side stream
    cudaEventRecord(ev_fork, 0);
    cudaStreamWaitEvent(s_side, ev_fork, 0);

    int ithr = (GNUM * 64 > N) ? GNUM * 64 : N;
    k_init<<<(ithr + 255) / 256, 256, 0, s_side>>>(N);
    k_deg<<<(E + 255) / 256, 256, 0, s_side>>>(dst, E);
    k_rsqrt<<<(N + 255) / 256, 256, 0, s_side>>>(N);
    k_scan1<<<NB, SCAN_B, 0, s_side>>>(N);
    k_scan2<<<1, 64, 0, s_side>>>(NB);
    k_scan3<<<(N + 255) / 256, 256, 0, s_side>>>(N);
    k_fill<<<(E + 255) / 256, 256, 0, s_side>>>(src, dst, E);
    k_prep_wc<<<(128 * 128 + 255) / 256, 256, 0, s_side>>>(W3, W4);

    // GEMM1 (full) on main, overlapping the CSR build; writes fp16 msgs only
    k_prep_w1<<<(128 * 256 + 255) / 256, 256>>>(W1);
    k_gemm_mma<<<(N + 127) / 128, 256, 49152>>>(x, w1h, w1l, h0hp, nullptr, N, 256);

    // join CSR before aggregates
    cudaEventRecord(ev_join, s_side);
    cudaStreamWaitEvent(0, ev_join, 0);

    // ---- pipelined agg1 / GEMM2 over two row chunks (70/30 split) ----
    // chunk0 aggregate (main)
    k_agg1<<<(Nh * 32 + 255) / 256, 256>>>(b1, 0, Nh);
    cudaEventRecord(ev_c0, 0);

    // chunk1 aggregate (side), concurrent with GEMM2 chunk0
    cudaStreamWaitEvent(s_side, ev_c0, 0);
    if (N > Nh) {
        k_agg1<<<((N - Nh) * 32 + 255) / 256, 256, 0, s_side>>>(b1, Nh, N);
    }
    cudaEventRecord(ev_a1, s_side);

    // GEMM2 chunk0 (main): rows [0, Nh)
    k_gemm_mma<<<(Nh + 127) / 128, 256, 49152>>>(
        hp, w2h, w2l, hwhp, disp, Nh, 128);

    // GEMM2 chunk1 after side aggregate completes
    cudaStreamWaitEvent(0, ev_a1, 0);
    if (N > Nh) {
        k_gemm_mma<<<((N - Nh) + 127) / 128, 256, 49152>>>(
            hp + (size_t)Nh * 128, w2h, w2l, hwhp + (size_t)Nh * 128,
            disp + Nh, N - Nh, 128);
    }

    // conv2 aggregate + reparam + pool, then head
    k_agg2<<<(N * 32 + 255) / 256, 256>>>(b3, b4, noise, batch, N);
    k_head<<<(GNUM * 32 + 255) / 256, 256>>>(Wfc, bfc, out);
}